// round 1
// baseline (speedup 1.0000x reference)
#include <cuda_runtime.h>

#define NN 50000
#define EE 800000
#define TPB 128
#define EGRID 1184
#define NGRID 400

typedef unsigned long long ull;

// -------- persistent device scratch (no allocations allowed) --------
__device__ float g_featA[NN * 64];
__device__ float g_featB[NN * 64];
__device__ float g_posA[NN * 3];
__device__ float g_posB[NN * 3];
__device__ float g_msg[NN * 64];
__device__ float g_pagg[NN * 3];
__device__ float g_inv[NN];
__device__ int   g_cnt[NN];

// -------- packed fp32x2 helpers (Blackwell FFMA2) --------
__device__ __forceinline__ ull fma2(ull a, ull b, ull c) {
    ull d;
    asm("fma.rn.f32x2 %0, %1, %2, %3;" : "=l"(d) : "l"(a), "l"(b), "l"(c));
    return d;
}
__device__ __forceinline__ ull pack2(float x) {
    ull r;
    asm("mov.b64 %0, {%1, %1};" : "=l"(r) : "f"(x));
    return r;
}
__device__ __forceinline__ float2 unpack2(ull v) {
    float2 f;
    asm("mov.b64 {%0, %1}, %2;" : "=f"(f.x), "=f"(f.y) : "l"(v));
    return f;
}
__device__ __forceinline__ float silu_f(float x) {
    return x * __fdividef(1.0f, 1.0f + __expf(-x));
}

// rank-1 update: acc[0..31] (64 outputs packed) += x * W[krow][0..63]
__device__ __forceinline__ void mac16(ull* acc, const ulonglong2* Wq, int krow, float x) {
    ull xx = pack2(x);
    const ulonglong2* wp = Wq + krow * 16;
#pragma unroll
    for (int jq = 0; jq < 16; ++jq) {
        ulonglong2 w = wp[jq];
        acc[2 * jq]     = fma2(xx, w.x, acc[2 * jq]);
        acc[2 * jq + 1] = fma2(xx, w.y, acc[2 * jq + 1]);
    }
}

// -------- edge kernel smem layout (floats) --------
#define E_SW1  0        // 131*64
#define E_SW2  8384     // 64*64
#define E_SPW1 12480    // 64*64
#define E_SB1  16576    // 64
#define E_SB2  16640    // 64
#define E_SPB1 16704    // 64
#define E_SPW2 16768    // 64
#define E_HBUF 16832    // 64*TPB
#define E_SMEMF (16832 + 64 * TPB)
#define E_SMEMB (E_SMEMF * 4)

// -------- node kernel smem layout (floats) --------
#define N_SW1  0        // 128*64
#define N_SW2  8192     // 64*64
#define N_SB1  12288
#define N_SB2  12352
#define N_HBUF 12416    // 64*TPB
#define N_SMEMF (12416 + 64 * TPB)
#define N_SMEMB (N_SMEMF * 4)

template <bool DO_MSG, bool DO_POS>
__global__ void __launch_bounds__(TPB)
edge_kernel(int featSel, int posSel,
            const float2* __restrict__ edge_attr,
            const int* __restrict__ row, const int* __restrict__ col,
            const float* __restrict__ W1, const float* __restrict__ b1,
            const float* __restrict__ W2, const float* __restrict__ b2,
            const float* __restrict__ PW1, const float* __restrict__ Pb1,
            const float* __restrict__ PW2, const float* __restrict__ Pb2)
{
    extern __shared__ float sm[];
    const int tid = threadIdx.x;

    for (int i = tid; i < 131 * 64; i += TPB) sm[E_SW1 + i] = W1[i];
    for (int i = tid; i < 64 * 64; i += TPB) sm[E_SW2 + i] = W2[i];
    if (DO_POS)
        for (int i = tid; i < 64 * 64; i += TPB) sm[E_SPW1 + i] = PW1[i];
    if (tid < 64) {
        sm[E_SB1 + tid] = b1[tid];
        sm[E_SB2 + tid] = b2[tid];
        if (DO_POS) { sm[E_SPB1 + tid] = Pb1[tid]; sm[E_SPW2 + tid] = PW2[tid]; }
    }
    float pb2v = DO_POS ? Pb2[0] : 0.0f;
    __syncthreads();

    const float* featIn = featSel ? g_featB : g_featA;
    const float* posIn  = posSel  ? g_posB  : g_posA;
    const ulonglong2* W1q  = (const ulonglong2*)(sm + E_SW1);
    const ulonglong2* W2q  = (const ulonglong2*)(sm + E_SW2);
    const ulonglong2* PW1q = (const ulonglong2*)(sm + E_SPW1);
    const ull* B1q  = (const ull*)(sm + E_SB1);
    const ull* B2q  = (const ull*)(sm + E_SB2);
    const ull* PB1q = (const ull*)(sm + E_SPB1);
    float* hb = sm + E_HBUF + tid;   // per-thread column, stride TPB

    for (int e = blockIdx.x * TPB + tid; e < EE; e += gridDim.x * TPB) {
        const int r = row[e], c = col[e];
        const float dx = posIn[r * 3 + 0] - posIn[c * 3 + 0];
        const float dy = posIn[r * 3 + 1] - posIn[c * 3 + 1];
        const float dz = posIn[r * 3 + 2] - posIn[c * 3 + 2];
        const float dist = dx * dx + dy * dy + dz * dz;

        // ---- stage 1: h1 = silu(h @ W1 + b1), h = [feat[r], feat[c], ea, dist]
        ull acc[32];
#pragma unroll
        for (int i = 0; i < 32; ++i) acc[i] = B1q[i];

        const float4* fr = (const float4*)(featIn + r * 64);
#pragma unroll 2
        for (int q = 0; q < 16; ++q) {
            float4 v = fr[q];
            mac16(acc, W1q, 4 * q + 0, v.x);
            mac16(acc, W1q, 4 * q + 1, v.y);
            mac16(acc, W1q, 4 * q + 2, v.z);
            mac16(acc, W1q, 4 * q + 3, v.w);
        }
        const float4* fc = (const float4*)(featIn + c * 64);
#pragma unroll 2
        for (int q = 0; q < 16; ++q) {
            float4 v = fc[q];
            mac16(acc, W1q, 64 + 4 * q + 0, v.x);
            mac16(acc, W1q, 64 + 4 * q + 1, v.y);
            mac16(acc, W1q, 64 + 4 * q + 2, v.z);
            mac16(acc, W1q, 64 + 4 * q + 3, v.w);
        }
        {
            float2 ea = edge_attr[e];
            mac16(acc, W1q, 128, ea.x);
            mac16(acc, W1q, 129, ea.y);
            mac16(acc, W1q, 130, dist);
        }
#pragma unroll
        for (int i = 0; i < 32; ++i) {
            float2 f = unpack2(acc[i]);
            hb[(2 * i) * TPB]     = silu_f(f.x);
            hb[(2 * i + 1) * TPB] = silu_f(f.y);
        }

        // ---- stage 2: msg = silu(h1 @ W2 + b2)
#pragma unroll
        for (int i = 0; i < 32; ++i) acc[i] = B2q[i];
#pragma unroll 4
        for (int k = 0; k < 64; ++k) mac16(acc, W2q, k, hb[k * TPB]);

        float* mrow = &g_msg[(size_t)r * 64];
#pragma unroll
        for (int i = 0; i < 32; ++i) {
            float2 f = unpack2(acc[i]);
            float m0 = silu_f(f.x), m1 = silu_f(f.y);
            if (DO_POS) { hb[(2 * i) * TPB] = m0; hb[(2 * i + 1) * TPB] = m1; }
            if (DO_MSG) { atomicAdd(mrow + 2 * i, m0); atomicAdd(mrow + 2 * i + 1, m1); }
        }

        // ---- stage 3: w = silu(msg @ PW1 + Pb1) . PW2 + Pb2 ; scatter diff*w
        if (DO_POS) {
#pragma unroll
            for (int i = 0; i < 32; ++i) acc[i] = PB1q[i];
#pragma unroll 4
            for (int k = 0; k < 64; ++k) mac16(acc, PW1q, k, hb[k * TPB]);
            float w = pb2v;
#pragma unroll
            for (int i = 0; i < 32; ++i) {
                float2 f = unpack2(acc[i]);
                w += silu_f(f.x) * sm[E_SPW2 + 2 * i] + silu_f(f.y) * sm[E_SPW2 + 2 * i + 1];
            }
            atomicAdd(&g_pagg[r * 3 + 0], dx * w);
            atomicAdd(&g_pagg[r * 3 + 1], dy * w);
            atomicAdd(&g_pagg[r * 3 + 2], dz * w);
        }
    }
}

template <bool DO_POS>
__global__ void __launch_bounds__(TPB)
node_kernel(int featSel, int posSel,
            const float* __restrict__ W1, const float* __restrict__ b1,
            const float* __restrict__ W2, const float* __restrict__ b2)
{
    extern __shared__ float sm[];
    const int tid = threadIdx.x;
    for (int i = tid; i < 128 * 64; i += TPB) sm[N_SW1 + i] = W1[i];
    for (int i = tid; i < 64 * 64; i += TPB) sm[N_SW2 + i] = W2[i];
    if (tid < 64) { sm[N_SB1 + tid] = b1[tid]; sm[N_SB2 + tid] = b2[tid]; }
    __syncthreads();

    const float* featIn = featSel ? g_featB : g_featA;
    float*       featOut = featSel ? g_featA : g_featB;
    const float* posIn  = posSel ? g_posB : g_posA;
    float*       posOut = posSel ? g_posA : g_posB;
    const ulonglong2* W1q = (const ulonglong2*)(sm + N_SW1);
    const ulonglong2* W2q = (const ulonglong2*)(sm + N_SW2);
    const ull* B1q = (const ull*)(sm + N_SB1);
    const ull* B2q = (const ull*)(sm + N_SB2);
    float* hb = sm + N_HBUF + tid;

    for (int n = blockIdx.x * TPB + tid; n < NN; n += gridDim.x * TPB) {
        float inv = g_inv[n];
        ull acc[32];
#pragma unroll
        for (int i = 0; i < 32; ++i) acc[i] = B1q[i];

        const float4* fr = (const float4*)(featIn + n * 64);
#pragma unroll 2
        for (int q = 0; q < 16; ++q) {
            float4 v = fr[q];
            mac16(acc, W1q, 4 * q + 0, v.x);
            mac16(acc, W1q, 4 * q + 1, v.y);
            mac16(acc, W1q, 4 * q + 2, v.z);
            mac16(acc, W1q, 4 * q + 3, v.w);
        }
        const float4* fm = (const float4*)(g_msg + (size_t)n * 64);
#pragma unroll 2
        for (int q = 0; q < 16; ++q) {
            float4 v = fm[q];
            mac16(acc, W1q, 64 + 4 * q + 0, v.x * inv);
            mac16(acc, W1q, 64 + 4 * q + 1, v.y * inv);
            mac16(acc, W1q, 64 + 4 * q + 2, v.z * inv);
            mac16(acc, W1q, 64 + 4 * q + 3, v.w * inv);
        }
#pragma unroll
        for (int i = 0; i < 32; ++i) {
            float2 f = unpack2(acc[i]);
            hb[(2 * i) * TPB]     = silu_f(f.x);
            hb[(2 * i + 1) * TPB] = silu_f(f.y);
        }
#pragma unroll
        for (int i = 0; i < 32; ++i) acc[i] = B2q[i];
#pragma unroll 4
        for (int k = 0; k < 64; ++k) mac16(acc, W2q, k, hb[k * TPB]);

        float2* fo = (float2*)(featOut + n * 64);
#pragma unroll
        for (int i = 0; i < 32; ++i) fo[i] = unpack2(acc[i]);   // no final activation

        if (DO_POS) {
            posOut[n * 3 + 0] = posIn[n * 3 + 0] + g_pagg[n * 3 + 0] * inv;
            posOut[n * 3 + 1] = posIn[n * 3 + 1] + g_pagg[n * 3 + 1] * inv;
            posOut[n * 3 + 2] = posIn[n * 3 + 2] + g_pagg[n * 3 + 2] * inv;
        }
    }
}

// -------- small helper kernels --------
__global__ void zero_aggr_kernel() {
    int i = blockIdx.x * blockDim.x + threadIdx.x;
    if (i < NN * 64) g_msg[i] = 0.0f;
    if (i < NN * 3)  g_pagg[i] = 0.0f;
    if (i < NN)      g_cnt[i] = 0;
}
__global__ void copy_pos_kernel(const float* __restrict__ p) {
    int i = blockIdx.x * blockDim.x + threadIdx.x;
    if (i < NN * 3) g_posB[i] = p[i];
}
__global__ void count_kernel(const int* __restrict__ row) {
    int e = blockIdx.x * blockDim.x + threadIdx.x;
    if (e < EE) atomicAdd(&g_cnt[row[e]], 1);
}
__global__ void inv_kernel() {
    int n = blockIdx.x * blockDim.x + threadIdx.x;
    if (n < NN) g_inv[n] = 1.0f / fmaxf((float)g_cnt[n], 1.0f);
}
__global__ void emb_kernel(const float* __restrict__ nf, const float* __restrict__ W,
                           const float* __restrict__ b) {
    int i = blockIdx.x * blockDim.x + threadIdx.x;
    if (i < NN * 64) {
        int n = i >> 6, j = i & 63;
        g_featA[i] = nf[2 * n] * W[j] + nf[2 * n + 1] * W[64 + j] + b[j];
    }
}
__global__ void pos_final_kernel(float* __restrict__ out) {
    int i = blockIdx.x * blockDim.x + threadIdx.x;
    if (i < NN * 3) {
        int n = i / 3;
        out[i] = g_posA[i] + g_pagg[i] * g_inv[n];
    }
}

extern "C" void kernel_launch(void* const* d_in, const int* in_sizes, int n_in,
                              void* d_out, int out_size)
{
    const float*  node_feat = (const float*)d_in[0];
    const float*  node_pos  = (const float*)d_in[1];
    const float2* edge_attr = (const float2*)d_in[2];
    const int*    row       = (const int*)d_in[3];
    const int*    col       = (const int*)d_in[4];
    const float*  emb_W     = (const float*)d_in[5];
    const float*  emb_b     = (const float*)d_in[6];
    const float*  mW1 = (const float*)d_in[7];
    const float*  mb1 = (const float*)d_in[8];
    const float*  mW2 = (const float*)d_in[9];
    const float*  mb2 = (const float*)d_in[10];
    const float*  pW1 = (const float*)d_in[11];
    const float*  pb1 = (const float*)d_in[12];
    const float*  pW2 = (const float*)d_in[13];
    const float*  pb2 = (const float*)d_in[14];
    const float*  nW1 = (const float*)d_in[15];
    const float*  nb1 = (const float*)d_in[16];
    const float*  nW2 = (const float*)d_in[17];
    const float*  nb2 = (const float*)d_in[18];
    float* out = (float*)d_out;

    cudaFuncSetAttribute(edge_kernel<true, false>, cudaFuncAttributeMaxDynamicSharedMemorySize, E_SMEMB);
    cudaFuncSetAttribute(edge_kernel<true, true>,  cudaFuncAttributeMaxDynamicSharedMemorySize, E_SMEMB);
    cudaFuncSetAttribute(edge_kernel<false, true>, cudaFuncAttributeMaxDynamicSharedMemorySize, E_SMEMB);
    cudaFuncSetAttribute(node_kernel<false>, cudaFuncAttributeMaxDynamicSharedMemorySize, N_SMEMB);
    cudaFuncSetAttribute(node_kernel<true>,  cudaFuncAttributeMaxDynamicSharedMemorySize, N_SMEMB);

    const int ZG = (NN * 64 + 255) / 256;

    // prelude: counts, inv, embedding, pos copy
    zero_aggr_kernel<<<ZG, 256>>>();
    copy_pos_kernel<<<(NN * 3 + 255) / 256, 256>>>(node_pos);
    count_kernel<<<(EE + 255) / 256, 256>>>(row);
    inv_kernel<<<(NN + 255) / 256, 256>>>();
    emb_kernel<<<ZG, 256>>>(node_feat, emb_W, emb_b);

#define EDGE_ARGS(l) edge_attr, row, col, \
        mW1 + (l) * 131 * 64, mb1 + (l) * 64, mW2 + (l) * 4096, mb2 + (l) * 64, \
        pW1 + (l) * 4096, pb1 + (l) * 64, pW2 + (l) * 64, pb2 + (l)
#define NODE_ARGS(l) nW1 + (l) * 128 * 64, nb1 + (l) * 64, nW2 + (l) * 4096, nb2 + (l) * 64

    // L0: com_node_feat_net layer — feat only (pos output discarded)
    edge_kernel<true, false><<<EGRID, TPB, E_SMEMB>>>(0, 1, EDGE_ARGS(0));
    node_kernel<false><<<NGRID, TPB, N_SMEMB>>>(0, 1, NODE_ARGS(0));

    // L1
    zero_aggr_kernel<<<ZG, 256>>>();
    edge_kernel<true, true><<<EGRID, TPB, E_SMEMB>>>(1, 1, EDGE_ARGS(1));
    node_kernel<true><<<NGRID, TPB, N_SMEMB>>>(1, 1, NODE_ARGS(1));

    // L2
    zero_aggr_kernel<<<ZG, 256>>>();
    edge_kernel<true, true><<<EGRID, TPB, E_SMEMB>>>(0, 0, EDGE_ARGS(2));
    node_kernel<true><<<NGRID, TPB, N_SMEMB>>>(0, 0, NODE_ARGS(2));

    // L3
    zero_aggr_kernel<<<ZG, 256>>>();
    edge_kernel<true, true><<<EGRID, TPB, E_SMEMB>>>(1, 1, EDGE_ARGS(3));
    node_kernel<true><<<NGRID, TPB, N_SMEMB>>>(1, 1, NODE_ARGS(3));

    // L4: final layer — only pos is returned; skip msg aggregation + node feat MLP
    zero_aggr_kernel<<<ZG, 256>>>();
    edge_kernel<false, true><<<EGRID, TPB, E_SMEMB>>>(0, 0, EDGE_ARGS(4));
    pos_final_kernel<<<(NN * 3 + 255) / 256, 256>>>(out);

#undef EDGE_ARGS
#undef NODE_ARGS
}

// round 3
// speedup vs baseline: 2.6898x; 2.6898x over previous
#include <cuda_runtime.h>
#include <cstdint>

#define NN 50000
#define EE 800000
#define ETPB 256
#define NTILES 3125        // EE / 256 exactly
#define EGRID 148
#define NTPB 128
#define NGRID 400

typedef unsigned long long ull;
typedef unsigned int u32;

// -------- persistent device scratch --------
__device__ float g_featA[NN * 64];
__device__ float g_featB[NN * 64];
__device__ float g_posA[NN * 3];
__device__ float g_posB[NN * 3];
__device__ float g_msg[NN * 64];
__device__ float g_pagg[NN * 3];
__device__ float g_inv[NN];
__device__ int   g_cnt[NN];

// -------- helpers --------
__device__ __forceinline__ float silu_f(float x) {
    return x * __fdividef(1.0f, 1.0f + __expf(-x));
}
__device__ __forceinline__ u32 f2tf(float x) {
    u32 r;
    asm("cvt.rna.tf32.f32 %0, %1;" : "=r"(r) : "f"(x));
    return r;
}
__device__ __forceinline__ float f2tf_f(float x) { return __uint_as_float(f2tf(x)); }

#define MMA8(d0, d1, d2, d3, a0, a1, a2, a3, b0, b1)                               \
    asm volatile("mma.sync.aligned.m16n8k8.row.col.f32.tf32.tf32.f32 "             \
                 "{%0,%1,%2,%3}, {%4,%5,%6,%7}, {%8,%9}, {%0,%1,%2,%3};"           \
                 : "+f"(d0), "+f"(d1), "+f"(d2), "+f"(d3)                          \
                 : "r"(a0), "r"(a1), "r"(a2), "r"(a3), "r"(b0), "r"(b1))

#define REDV2(p, a, b)                                                             \
    asm volatile("red.global.add.v2.f32 [%0], {%1, %2};" :: "l"(p), "f"(a), "f"(b) : "memory")

// -------- edge kernel SMEM layout (byte offsets) --------
// W1s [128][72] f32(tf32)  @ 0       36864
// W2s [64][72]             @ 36864   18432
// P1s [64][72]             @ 55296   18432
// A1R [256][68]            @ 73728   69632
// A1C [256][68]            @ 143360  69632
// ESdx/dy/dz/ds/ex/ey [256]@ 212992  6*1024
// ESr [256] int            @ 219136  1024
// sxT float4[64]           @ 220160  1024   (W1[128], W1[129], W1[130], b1) per col
// sxB2 float[64]           @ 221184  256
// sxP float2[64]           @ 221440  512    (pb1, pW2)
#define SM_EDGE_TOTAL 221952

__device__ __forceinline__ void gemm_stage(float acc[2][8][4], const u32* As, const u32* Bs,
                                           int tb, int g, int cc, int nkt)
{
    for (int kt = 0; kt < nkt; ++kt) {
        const u32* Ws = Bs + kt * 8 * 72;
        u32 b0[8], b1[8];
#pragma unroll
        for (int nt = 0; nt < 8; ++nt) {
            b0[nt] = Ws[cc * 72 + nt * 8 + g];
            b1[nt] = Ws[(cc + 4) * 72 + nt * 8 + g];
        }
#pragma unroll
        for (int mt = 0; mt < 2; ++mt) {
            int base = (tb + mt * 16 + g) * 68 + kt * 8 + cc;
            u32 a0 = As[base], a1 = As[base + 8 * 68], a2 = As[base + 4], a3 = As[base + 8 * 68 + 4];
#pragma unroll
            for (int nt = 0; nt < 8; ++nt)
                MMA8(acc[mt][nt][0], acc[mt][nt][1], acc[mt][nt][2], acc[mt][nt][3],
                     a0, a1, a2, a3, b0[nt], b1[nt]);
        }
    }
}

template <bool DO_MSG, bool DO_POS>
__global__ void __launch_bounds__(ETPB, 1)
edge_kernel(int featSel, int posSel,
            const float2* __restrict__ ea_g,
            const int* __restrict__ row, const int* __restrict__ col,
            const float* __restrict__ mW1, const float* __restrict__ mb1,
            const float* __restrict__ mW2, const float* __restrict__ mb2,
            const float* __restrict__ pW1, const float* __restrict__ pb1,
            const float* __restrict__ pW2, const float* __restrict__ pb2)
{
    extern __shared__ __align__(16) char sm[];
    float*  W1s  = (float*)(sm);
    float*  W2s  = (float*)(sm + 36864);
    float*  P1s  = (float*)(sm + 55296);
    float*  A1R  = (float*)(sm + 73728);
    float*  A1C  = (float*)(sm + 143360);
    float*  ESdx = (float*)(sm + 212992);
    float*  ESdy = (float*)(sm + 214016);
    float*  ESdz = (float*)(sm + 215040);
    float*  ESds = (float*)(sm + 216064);
    float*  ESex = (float*)(sm + 217088);
    float*  ESey = (float*)(sm + 218112);
    int*    ESr  = (int*)  (sm + 219136);
    float4* sxT  = (float4*)(sm + 220160);
    float*  sxB2 = (float*)(sm + 221184);
    float2* sxP  = (float2*)(sm + 221440);

    const int tid = threadIdx.x;

    // ---- stage weights (cvt.rna to tf32 bits, stored as f32) ----
    for (int i = tid; i < 128 * 64; i += ETPB) {
        int k = i >> 6, n = i & 63;
        W1s[k * 72 + n] = f2tf_f(mW1[i]);
    }
    for (int i = tid; i < 64 * 64; i += ETPB) {
        int k = i >> 6, n = i & 63;
        W2s[k * 72 + n] = f2tf_f(mW2[i]);
        P1s[k * 72 + n] = f2tf_f(pW1[i]);
    }
    if (tid < 64) {
        sxT[tid] = make_float4(mW1[128 * 64 + tid], mW1[129 * 64 + tid], mW1[130 * 64 + tid], mb1[tid]);
        sxB2[tid] = mb2[tid];
        sxP[tid] = make_float2(pb1[tid], pW2[tid]);
    }
    const float pb2v = pb2[0];
    __syncthreads();

    const float* featIn = featSel ? g_featB : g_featA;
    const float* posIn  = posSel  ? g_posB  : g_posA;

    const int lane = tid & 31;
    const int g  = lane >> 2;
    const int cc = lane & 3;
    const int tb = (tid >> 5) * 32;      // this warp's 32 rows of the tile

    for (int tile = blockIdx.x; tile < NTILES; tile += gridDim.x) {
        __syncwarp();
        // ---- prologue: per-thread edge ----
        const int e = tile * ETPB + tid;
        const int r = row[e], c = col[e];
        const float dx = posIn[r * 3 + 0] - posIn[c * 3 + 0];
        const float dy = posIn[r * 3 + 1] - posIn[c * 3 + 1];
        const float dz = posIn[r * 3 + 2] - posIn[c * 3 + 2];
        const float dist = dx * dx + dy * dy + dz * dz;
        const float2 ea = ea_g[e];
        ESdx[tid] = dx; ESdy[tid] = dy; ESdz[tid] = dz;
        ESds[tid] = dist; ESex[tid] = ea.x; ESey[tid] = ea.y;
        ESr[tid] = r;
        {
            const float4* fr4 = (const float4*)(featIn + (size_t)r * 64);
            const float4* fc4 = (const float4*)(featIn + (size_t)c * 64);
            float4* aR = (float4*)(A1R + tid * 68);
            float4* aC = (float4*)(A1C + tid * 68);
#pragma unroll
            for (int q = 0; q < 16; ++q) { aR[q] = fr4[q]; aC[q] = fc4[q]; }
        }
        __syncwarp();

        float acc[2][8][4];
#pragma unroll
        for (int mt = 0; mt < 2; ++mt)
#pragma unroll
            for (int nt = 0; nt < 8; ++nt)
#pragma unroll
                for (int i = 0; i < 4; ++i) acc[mt][nt][i] = 0.0f;

        // ---- stage 1: h1_pre = [featR | featC] @ W1[0:128] ----
        gemm_stage(acc, (const u32*)A1R, (const u32*)W1s, tb, g, cc, 8);
        gemm_stage(acc, (const u32*)A1C, (const u32*)(W1s + 64 * 72), tb, g, cc, 8);

        // ---- epilogue 1: tail (ea, dist, b1) + silu -> h1 into A1R (tf32) ----
#pragma unroll
        for (int mt = 0; mt < 2; ++mt) {
            const int e0 = tb + mt * 16 + g, e1 = e0 + 8;
            const float ex0 = ESex[e0], ey0 = ESey[e0], ds0 = ESds[e0];
            const float ex1 = ESex[e1], ey1 = ESey[e1], ds1 = ESds[e1];
#pragma unroll
            for (int nt = 0; nt < 8; ++nt) {
                const int n0 = nt * 8 + 2 * cc;
                const float4 t0 = sxT[n0], t1 = sxT[n0 + 1];
                float v00 = silu_f(acc[mt][nt][0] + t0.w + ex0 * t0.x + ey0 * t0.y + ds0 * t0.z);
                float v01 = silu_f(acc[mt][nt][1] + t1.w + ex0 * t1.x + ey0 * t1.y + ds0 * t1.z);
                float v10 = silu_f(acc[mt][nt][2] + t0.w + ex1 * t0.x + ey1 * t0.y + ds1 * t0.z);
                float v11 = silu_f(acc[mt][nt][3] + t1.w + ex1 * t1.x + ey1 * t1.y + ds1 * t1.z);
                *(uint2*)(A1R + e0 * 68 + n0) = make_uint2(f2tf(v00), f2tf(v01));
                *(uint2*)(A1R + e1 * 68 + n0) = make_uint2(f2tf(v10), f2tf(v11));
            }
        }
        __syncwarp();

        // ---- stage 2: msg_pre = h1 @ W2 ----
#pragma unroll
        for (int mt = 0; mt < 2; ++mt)
#pragma unroll
            for (int nt = 0; nt < 8; ++nt)
#pragma unroll
                for (int i = 0; i < 4; ++i) acc[mt][nt][i] = 0.0f;
        gemm_stage(acc, (const u32*)A1R, (const u32*)W2s, tb, g, cc, 8);

        // ---- epilogue 2: silu -> msg; red.v2 scatter; msg(tf32) -> A1C ----
#pragma unroll
        for (int mt = 0; mt < 2; ++mt) {
            const int e0 = tb + mt * 16 + g, e1 = e0 + 8;
            const int r0 = ESr[e0], r1 = ESr[e1];
#pragma unroll
            for (int nt = 0; nt < 8; ++nt) {
                const int n0 = nt * 8 + 2 * cc;
                float m00 = silu_f(acc[mt][nt][0] + sxB2[n0]);
                float m01 = silu_f(acc[mt][nt][1] + sxB2[n0 + 1]);
                float m10 = silu_f(acc[mt][nt][2] + sxB2[n0]);
                float m11 = silu_f(acc[mt][nt][3] + sxB2[n0 + 1]);
                if (DO_MSG) {
                    REDV2(g_msg + (size_t)r0 * 64 + n0, m00, m01);
                    REDV2(g_msg + (size_t)r1 * 64 + n0, m10, m11);
                }
                if (DO_POS) {
                    *(uint2*)(A1C + e0 * 68 + n0) = make_uint2(f2tf(m00), f2tf(m01));
                    *(uint2*)(A1C + e1 * 68 + n0) = make_uint2(f2tf(m10), f2tf(m11));
                }
            }
        }

        if (DO_POS) {
            __syncwarp();
            // ---- stage 3: p1_pre = msg @ PW1 ----
#pragma unroll
            for (int mt = 0; mt < 2; ++mt)
#pragma unroll
                for (int nt = 0; nt < 8; ++nt)
#pragma unroll
                    for (int i = 0; i < 4; ++i) acc[mt][nt][i] = 0.0f;
            gemm_stage(acc, (const u32*)A1C, (const u32*)P1s, tb, g, cc, 8);

            // ---- epilogue 3: w = silu(. + pb1) . pW2 + pb2; scatter diff*w ----
#pragma unroll
            for (int mt = 0; mt < 2; ++mt) {
                float w0 = 0.0f, w1 = 0.0f;
#pragma unroll
                for (int nt = 0; nt < 8; ++nt) {
                    const int n0 = nt * 8 + 2 * cc;
                    const float2 p0 = sxP[n0], p1 = sxP[n0 + 1];
                    w0 += silu_f(acc[mt][nt][0] + p0.x) * p0.y + silu_f(acc[mt][nt][1] + p1.x) * p1.y;
                    w1 += silu_f(acc[mt][nt][2] + p0.x) * p0.y + silu_f(acc[mt][nt][3] + p1.x) * p1.y;
                }
                w0 += __shfl_xor_sync(0xffffffffu, w0, 1);
                w0 += __shfl_xor_sync(0xffffffffu, w0, 2);
                w1 += __shfl_xor_sync(0xffffffffu, w1, 1);
                w1 += __shfl_xor_sync(0xffffffffu, w1, 2);
                if (cc == 0) {
                    const int e0 = tb + mt * 16 + g, e1 = e0 + 8;
                    const float wa = w0 + pb2v, wb = w1 + pb2v;
                    const int r0 = ESr[e0], r1 = ESr[e1];
                    atomicAdd(&g_pagg[r0 * 3 + 0], ESdx[e0] * wa);
                    atomicAdd(&g_pagg[r0 * 3 + 1], ESdy[e0] * wa);
                    atomicAdd(&g_pagg[r0 * 3 + 2], ESdz[e0] * wa);
                    atomicAdd(&g_pagg[r1 * 3 + 0], ESdx[e1] * wb);
                    atomicAdd(&g_pagg[r1 * 3 + 1], ESdy[e1] * wb);
                    atomicAdd(&g_pagg[r1 * 3 + 2], ESdz[e1] * wb);
                }
            }
        }
    }
}

// ================= node kernel (SIMT FFMA2, f32) =================
__device__ __forceinline__ ull fma2(ull a, ull b, ull c) {
    ull d;
    asm("fma.rn.f32x2 %0, %1, %2, %3;" : "=l"(d) : "l"(a), "l"(b), "l"(c));
    return d;
}
__device__ __forceinline__ ull pack2(float x) {
    ull r;
    asm("mov.b64 %0, {%1, %1};" : "=l"(r) : "f"(x));
    return r;
}
__device__ __forceinline__ float2 unpack2(ull v) {
    float2 f;
    asm("mov.b64 {%0, %1}, %2;" : "=f"(f.x), "=f"(f.y) : "l"(v));
    return f;
}
__device__ __forceinline__ void mac16(ull* acc, const ulonglong2* Wq, int krow, float x) {
    ull xx = pack2(x);
    const ulonglong2* wp = Wq + krow * 16;
#pragma unroll
    for (int jq = 0; jq < 16; ++jq) {
        ulonglong2 w = wp[jq];
        acc[2 * jq]     = fma2(xx, w.x, acc[2 * jq]);
        acc[2 * jq + 1] = fma2(xx, w.y, acc[2 * jq + 1]);
    }
}

#define N_SW1  0
#define N_SW2  8192
#define N_SB1  12288
#define N_SB2  12352
#define N_HBUF 12416
#define N_SMEMB ((12416 + 64 * NTPB) * 4)

template <bool DO_POS>
__global__ void __launch_bounds__(NTPB)
node_kernel(int featSel, int posSel,
            const float* __restrict__ W1, const float* __restrict__ b1,
            const float* __restrict__ W2, const float* __restrict__ b2)
{
    extern __shared__ float smf[];
    const int tid = threadIdx.x;
    for (int i = tid; i < 128 * 64; i += NTPB) smf[N_SW1 + i] = W1[i];
    for (int i = tid; i < 64 * 64; i += NTPB) smf[N_SW2 + i] = W2[i];
    if (tid < 64) { smf[N_SB1 + tid] = b1[tid]; smf[N_SB2 + tid] = b2[tid]; }
    __syncthreads();

    const float* featIn  = featSel ? g_featB : g_featA;
    float*       featOut = featSel ? g_featA : g_featB;
    const float* posIn   = posSel ? g_posB : g_posA;
    float*       posOut  = posSel ? g_posA : g_posB;
    const ulonglong2* W1q = (const ulonglong2*)(smf + N_SW1);
    const ulonglong2* W2q = (const ulonglong2*)(smf + N_SW2);
    const ull* B1q = (const ull*)(smf + N_SB1);
    const ull* B2q = (const ull*)(smf + N_SB2);
    float* hb = smf + N_HBUF + tid;

    for (int n = blockIdx.x * NTPB + tid; n < NN; n += gridDim.x * NTPB) {
        const float inv = g_inv[n];
        ull acc[32];
#pragma unroll
        for (int i = 0; i < 32; ++i) acc[i] = B1q[i];

        const float4* fr = (const float4*)(featIn + (size_t)n * 64);
#pragma unroll 2
        for (int q = 0; q < 16; ++q) {
            float4 v = fr[q];
            mac16(acc, W1q, 4 * q + 0, v.x);
            mac16(acc, W1q, 4 * q + 1, v.y);
            mac16(acc, W1q, 4 * q + 2, v.z);
            mac16(acc, W1q, 4 * q + 3, v.w);
        }
        float4* fm = (float4*)(g_msg + (size_t)n * 64);
#pragma unroll 2
        for (int q = 0; q < 16; ++q) {
            float4 v = fm[q];
            mac16(acc, W1q, 64 + 4 * q + 0, v.x * inv);
            mac16(acc, W1q, 64 + 4 * q + 1, v.y * inv);
            mac16(acc, W1q, 64 + 4 * q + 2, v.z * inv);
            mac16(acc, W1q, 64 + 4 * q + 3, v.w * inv);
        }
        const float4 z4 = make_float4(0.f, 0.f, 0.f, 0.f);
#pragma unroll
        for (int q = 0; q < 16; ++q) fm[q] = z4;   // zero msg for next layer

#pragma unroll
        for (int i = 0; i < 32; ++i) {
            float2 f = unpack2(acc[i]);
            hb[(2 * i) * NTPB]     = silu_f(f.x);
            hb[(2 * i + 1) * NTPB] = silu_f(f.y);
        }
#pragma unroll
        for (int i = 0; i < 32; ++i) acc[i] = B2q[i];
#pragma unroll 4
        for (int k = 0; k < 64; ++k) mac16(acc, W2q, k, hb[k * NTPB]);

        float* fo = featOut + (size_t)n * 64;
#pragma unroll
        for (int i = 0; i < 32; ++i) {
            float2 f = unpack2(acc[i]);
            fo[2 * i]     = f2tf_f(f.x);   // rna-round so edge kernel can use raw bits
            fo[2 * i + 1] = f2tf_f(f.y);
        }

        if (DO_POS) {
            posOut[n * 3 + 0] = posIn[n * 3 + 0] + g_pagg[n * 3 + 0] * inv;
            posOut[n * 3 + 1] = posIn[n * 3 + 1] + g_pagg[n * 3 + 1] * inv;
            posOut[n * 3 + 2] = posIn[n * 3 + 2] + g_pagg[n * 3 + 2] * inv;
        }
        g_pagg[n * 3 + 0] = 0.f;
        g_pagg[n * 3 + 1] = 0.f;
        g_pagg[n * 3 + 2] = 0.f;
    }
}

// ================= helper kernels =================
__global__ void init_kernel(const float* __restrict__ pos) {
    int i = blockIdx.x * blockDim.x + threadIdx.x;
    if (i < NN * 64) g_msg[i] = 0.0f;
    if (i < NN * 3) { g_pagg[i] = 0.0f; g_posB[i] = pos[i]; }
    if (i < NN) g_cnt[i] = 0;
}
__global__ void count_kernel(const int* __restrict__ row) {
    int e = blockIdx.x * blockDim.x + threadIdx.x;
    if (e < EE) atomicAdd(&g_cnt[row[e]], 1);
}
__global__ void prep_kernel(const float* __restrict__ nf, const float* __restrict__ embW,
                            const float* __restrict__ embb) {
    int i = blockIdx.x * blockDim.x + threadIdx.x;
    if (i < NN) g_inv[i] = 1.0f / fmaxf((float)g_cnt[i], 1.0f);
    if (i < NN * 64) {
        int n = i >> 6, j = i & 63;
        float v = nf[2 * n] * embW[j] + nf[2 * n + 1] * embW[64 + j] + embb[j];
        g_featA[i] = f2tf_f(v);
    }
}
__global__ void pos_final_kernel(float* __restrict__ out) {
    int i = blockIdx.x * blockDim.x + threadIdx.x;
    if (i < NN * 3) {
        int n = i / 3;
        out[i] = g_posA[i] + g_pagg[i] * g_inv[n];
    }
}

extern "C" void kernel_launch(void* const* d_in, const int* in_sizes, int n_in,
                              void* d_out, int out_size)
{
    const float*  node_feat = (const float*)d_in[0];
    const float*  node_pos  = (const float*)d_in[1];
    const float2* edge_attr = (const float2*)d_in[2];
    const int*    row       = (const int*)d_in[3];
    const int*    col       = (const int*)d_in[4];
    const float*  emb_W     = (const float*)d_in[5];
    const float*  emb_b     = (const float*)d_in[6];
    const float*  mW1 = (const float*)d_in[7];
    const float*  mb1 = (const float*)d_in[8];
    const float*  mW2 = (const float*)d_in[9];
    const float*  mb2 = (const float*)d_in[10];
    const float*  pW1 = (const float*)d_in[11];
    const float*  pb1 = (const float*)d_in[12];
    const float*  pW2 = (const float*)d_in[13];
    const float*  pb2 = (const float*)d_in[14];
    const float*  nW1 = (const float*)d_in[15];
    const float*  nb1 = (const float*)d_in[16];
    const float*  nW2 = (const float*)d_in[17];
    const float*  nb2 = (const float*)d_in[18];
    float* out = (float*)d_out;

    cudaFuncSetAttribute(edge_kernel<true, false>, cudaFuncAttributeMaxDynamicSharedMemorySize, SM_EDGE_TOTAL);
    cudaFuncSetAttribute(edge_kernel<true, true>,  cudaFuncAttributeMaxDynamicSharedMemorySize, SM_EDGE_TOTAL);
    cudaFuncSetAttribute(edge_kernel<false, true>, cudaFuncAttributeMaxDynamicSharedMemorySize, SM_EDGE_TOTAL);
    cudaFuncSetAttribute(node_kernel<false>, cudaFuncAttributeMaxDynamicSharedMemorySize, N_SMEMB);
    cudaFuncSetAttribute(node_kernel<true>,  cudaFuncAttributeMaxDynamicSharedMemorySize, N_SMEMB);

    const int ZG = (NN * 64 + 255) / 256;

    init_kernel<<<ZG, 256>>>(node_pos);
    count_kernel<<<(EE + 255) / 256, 256>>>(row);
    prep_kernel<<<ZG, 256>>>(node_feat, emb_W, emb_b);

#define EDGE_ARGS(l) edge_attr, row, col, \
        mW1 + (l) * 131 * 64, mb1 + (l) * 64, mW2 + (l) * 4096, mb2 + (l) * 64, \
        pW1 + (l) * 4096, pb1 + (l) * 64, pW2 + (l) * 64, pb2 + (l)
#define NODE_ARGS(l) nW1 + (l) * 128 * 64, nb1 + (l) * 64, nW2 + (l) * 4096, nb2 + (l) * 64

    // L0 (com_node_feat_net): feat only
    edge_kernel<true, false><<<EGRID, ETPB, SM_EDGE_TOTAL>>>(0, 1, EDGE_ARGS(0));
    node_kernel<false><<<NGRID, NTPB, N_SMEMB>>>(0, 1, NODE_ARGS(0));
    // L1
    edge_kernel<true, true><<<EGRID, ETPB, SM_EDGE_TOTAL>>>(1, 1, EDGE_ARGS(1));
    node_kernel<true><<<NGRID, NTPB, N_SMEMB>>>(1, 1, NODE_ARGS(1));
    // L2
    edge_kernel<true, true><<<EGRID, ETPB, SM_EDGE_TOTAL>>>(0, 0, EDGE_ARGS(2));
    node_kernel<true><<<NGRID, NTPB, N_SMEMB>>>(0, 0, NODE_ARGS(2));
    // L3
    edge_kernel<true, true><<<EGRID, ETPB, SM_EDGE_TOTAL>>>(1, 1, EDGE_ARGS(3));
    node_kernel<true><<<NGRID, NTPB, N_SMEMB>>>(1, 1, NODE_ARGS(3));
    // L4: pos only
    edge_kernel<false, true><<<EGRID, ETPB, SM_EDGE_TOTAL>>>(0, 0, EDGE_ARGS(4));
    pos_final_kernel<<<(NN * 3 + 255) / 256, 256>>>(out);

#undef EDGE_ARGS
#undef NODE_ARGS
}

// round 7
// speedup vs baseline: 3.0016x; 1.1159x over previous
#include <cuda_runtime.h>
#include <cstdint>

#define NN 50000
#define EE 800000
#define ETPB 256
#define NTILES 3125        // EE / 256 exactly
#define EGRID 296
#define NTPB 128
#define NGRID 400

typedef unsigned long long ull;
typedef unsigned int u32;

// -------- persistent device scratch (f32 feat; bf16 only as raw u32 words) --------
__device__ float g_featA[NN * 64];
__device__ float g_featB[NN * 64];
__device__ float g_posA[NN * 3];
__device__ float g_posB[NN * 3];
__device__ float g_msg[NN * 64];
__device__ float g_pagg[NN * 3];
__device__ float g_inv[NN];
__device__ int   g_cnt[NN];
__device__ u32   g_wb[5 * 8192];  // per layer: W1t 64n x 64w, W2t 64n x 32w, P1t 64n x 32w (bf16x2 words: word w = cols 2w,2w+1)

// -------- helpers (no cuda_bf16.h anywhere) --------
__device__ __forceinline__ float silu_f(float x) {
    return x * __fdividef(1.0f, 1.0f + __expf(-x));
}
// pack two f32 -> bf16x2 word: lo -> low half (col 2w), hi -> high half (col 2w+1)
__device__ __forceinline__ u32 pk2(float lo, float hi) {
    u32 r;
    asm("cvt.rn.bf16x2.f32 %0, %1, %2;" : "=r"(r) : "f"(hi), "f"(lo));
    return r;
}

#define MMAB(d, a0, a1, a2, a3, b0, b1)                                            \
    asm volatile("mma.sync.aligned.m16n8k16.row.col.f32.bf16.bf16.f32 "            \
                 "{%0,%1,%2,%3}, {%4,%5,%6,%7}, {%8,%9}, {%0,%1,%2,%3};"           \
                 : "+f"((d)[0]), "+f"((d)[1]), "+f"((d)[2]), "+f"((d)[3])          \
                 : "r"(a0), "r"(a1), "r"(a2), "r"(a3), "r"(b0), "r"(b1))

#define REDV2(p, a, b)                                                             \
    asm volatile("red.global.add.v2.f32 [%0], {%1, %2};" :: "l"(p), "f"(a), "f"(b) : "memory")

#define SHF(v, src) __shfl_sync(0xffffffffu, (v), (src))

// -------- edge kernel SMEM layout (byte offsets), ETPB=256 --------
// W1s [64n][68w]  @0        17408   (stride 68 == 4 mod 32, frag loads conflict-free)
// W2s [64n][36w]  @17408    9216
// P1s [64n][36w]  @26624    9216
// A_R [256][36w]  @35840    36864   (stride 36 == 4 mod 32)
// A_C [256][36w]  @72704    36864
// sxT float4[64]  @109568   1024
// sxB2 float[64]  @110592   256
// sxP float2[64]  @110848   512
#define O_W1   0
#define O_W2   17408
#define O_P1   26624
#define O_AR   35840
#define O_AC   72704
#define O_SXT  109568
#define O_SB2  110592
#define O_SXP  110848
#define SM_TOT 111360

// one k16 step: 16 MMAs; all fragments are single 32-bit shared words (natural k-pair order)
__device__ __forceinline__ void stepK(float acc[2][8][4], const u32* A, const u32* B,
                                      int Astride, int Bstride, int kwA, int kwB,
                                      int tb, int g, int cc)
{
    u32 b0[8], b1[8];
#pragma unroll
    for (int nt = 0; nt < 8; ++nt) {
        const u32* br = B + (nt * 8 + g) * Bstride + kwB;
        b0[nt] = br[cc];
        b1[nt] = br[4 + cc];
    }
#pragma unroll
    for (int mt = 0; mt < 2; ++mt) {
        const u32* ar = A + (tb + mt * 16 + g) * Astride + kwA;
        u32 a0 = ar[cc];
        u32 a1 = ar[8 * Astride + cc];
        u32 a2 = ar[4 + cc];
        u32 a3 = ar[8 * Astride + 4 + cc];
#pragma unroll
        for (int nt = 0; nt < 8; ++nt)
            MMAB(acc[mt][nt], a0, a1, a2, a3, b0[nt], b1[nt]);
    }
}

template <bool DO_MSG, bool DO_POS>
__global__ void __launch_bounds__(ETPB)
edge_kernel(int featSel, int posSel, int layer,
            const float2* __restrict__ ea_g,
            const int* __restrict__ row, const int* __restrict__ col,
            const float* __restrict__ mW1, const float* __restrict__ mb1,
            const float* __restrict__ mb2, const float* __restrict__ pb1,
            const float* __restrict__ pW2, const float* __restrict__ pb2)
{
    extern __shared__ __align__(16) char sm[];
    u32*    W1s  = (u32*)(sm + O_W1);
    u32*    W2s  = (u32*)(sm + O_W2);
    u32*    P1s  = (u32*)(sm + O_P1);
    u32*    A_R  = (u32*)(sm + O_AR);
    u32*    A_C  = (u32*)(sm + O_AC);
    float4* sxT  = (float4*)(sm + O_SXT);
    float*  sxB2 = (float*)(sm + O_SB2);
    float2* sxP  = (float2*)(sm + O_SXP);

    const int tid = threadIdx.x;

    // ---- stage weights (bf16x2 words) ----
    {
        const u32* wsrc = g_wb + layer * 8192;
        for (int i = tid; i < 4096; i += ETPB) {
            int n = i >> 6, w = i & 63;
            W1s[n * 68 + w] = wsrc[i];
        }
        for (int i = tid; i < 2048; i += ETPB) {
            int n = i >> 5, w = i & 31;
            W2s[n * 36 + w] = wsrc[4096 + i];
            P1s[n * 36 + w] = wsrc[6144 + i];
        }
    }
    if (tid < 64) {
        sxT[tid] = make_float4(mW1[128 * 64 + tid], mW1[129 * 64 + tid], mW1[130 * 64 + tid], mb1[tid]);
        sxB2[tid] = mb2[tid];
        sxP[tid] = make_float2(pb1[tid], pW2[tid]);
    }
    const float pb2v = pb2[0];
    __syncthreads();

    const float* featIn = featSel ? g_featB : g_featA;
    const float* posIn  = posSel  ? g_posB  : g_posA;

    const int lane = tid & 31;
    const int g  = lane >> 2;
    const int cc = lane & 3;
    const int tb = (tid >> 5) * 32;

    for (int tile = blockIdx.x; tile < NTILES; tile += gridDim.x) {
        __syncwarp();
        // ---- prologue: per-thread edge (values stay in registers; shuffled later) ----
        const int e = tile * ETPB + tid;
        const int r = row[e], c = col[e];
        const float dx = posIn[r * 3 + 0] - posIn[c * 3 + 0];
        const float dy = posIn[r * 3 + 1] - posIn[c * 3 + 1];
        const float dz = posIn[r * 3 + 2] - posIn[c * 3 + 2];
        const float dist = dx * dx + dy * dy + dz * dz;
        const float2 ea = ea_g[e];

        // gather feat rows (f32 -> bf16x2 words) into A tiles
        {
            const float4* fr4 = (const float4*)(featIn + (size_t)r * 64);
            const float4* fc4 = (const float4*)(featIn + (size_t)c * 64);
            u32* aR = A_R + tid * 36;
            u32* aC = A_C + tid * 36;
#pragma unroll
            for (int q = 0; q < 16; ++q) {
                float4 v = fr4[q];
                *(uint2*)(aR + 2 * q) = make_uint2(pk2(v.x, v.y), pk2(v.z, v.w));
                float4 w = fc4[q];
                *(uint2*)(aC + 2 * q) = make_uint2(pk2(w.x, w.y), pk2(w.z, w.w));
            }
        }
        __syncwarp();

        float acc[2][8][4];
#pragma unroll
        for (int mt = 0; mt < 2; ++mt)
#pragma unroll
            for (int nt = 0; nt < 8; ++nt)
#pragma unroll
                for (int i = 0; i < 4; ++i) acc[mt][nt][i] = 0.0f;

        // ---- stage 1: h1_pre = featR @ W1[0:64] + featC @ W1[64:128] ----
#pragma unroll
        for (int kt = 0; kt < 4; ++kt) stepK(acc, A_R, W1s, 36, 68, kt * 8, kt * 8, tb, g, cc);
#pragma unroll
        for (int kt = 0; kt < 4; ++kt) stepK(acc, A_C, W1s, 36, 68, kt * 8, 32 + kt * 8, tb, g, cc);

        // ---- epilogue 1: tail (ea, dist, b1) + silu -> h1 (bf16 words) into A_R ----
#pragma unroll
        for (int mt = 0; mt < 2; ++mt) {
            const int q0 = mt * 16 + g, q1 = q0 + 8;     // warp-local rows
            const float ex0 = SHF(ea.x, q0), ey0 = SHF(ea.y, q0), ds0 = SHF(dist, q0);
            const float ex1 = SHF(ea.x, q1), ey1 = SHF(ea.y, q1), ds1 = SHF(dist, q1);
            const int e0 = tb + q0, e1 = tb + q1;
#pragma unroll
            for (int nt = 0; nt < 8; ++nt) {
                const int n0 = nt * 8 + 2 * cc;
                const float4 t0 = sxT[n0], t1 = sxT[n0 + 1];
                float v00 = silu_f(acc[mt][nt][0] + t0.w + ex0 * t0.x + ey0 * t0.y + ds0 * t0.z);
                float v01 = silu_f(acc[mt][nt][1] + t1.w + ex0 * t1.x + ey0 * t1.y + ds0 * t1.z);
                float v10 = silu_f(acc[mt][nt][2] + t0.w + ex1 * t0.x + ey1 * t0.y + ds1 * t0.z);
                float v11 = silu_f(acc[mt][nt][3] + t1.w + ex1 * t1.x + ey1 * t1.y + ds1 * t1.z);
                const int word = nt * 4 + cc;
                A_R[e0 * 36 + word] = pk2(v00, v01);
                A_R[e1 * 36 + word] = pk2(v10, v11);
            }
        }
        __syncwarp();

        // ---- stage 2: msg_pre = h1 @ W2 ----
#pragma unroll
        for (int mt = 0; mt < 2; ++mt)
#pragma unroll
            for (int nt = 0; nt < 8; ++nt)
#pragma unroll
                for (int i = 0; i < 4; ++i) acc[mt][nt][i] = 0.0f;
#pragma unroll
        for (int kt = 0; kt < 4; ++kt) stepK(acc, A_R, W2s, 36, 36, kt * 8, kt * 8, tb, g, cc);

        // ---- epilogue 2: silu -> msg; red.v2 scatter; msg (bf16) -> A_C ----
        int r0s[2], r1s[2];
#pragma unroll
        for (int mt = 0; mt < 2; ++mt) {
            const int q0 = mt * 16 + g, q1 = q0 + 8;
            const int r0 = SHF(r, q0), r1 = SHF(r, q1);
            r0s[mt] = r0; r1s[mt] = r1;
            const int e0 = tb + q0, e1 = tb + q1;
#pragma unroll
            for (int nt = 0; nt < 8; ++nt) {
                const int n0 = nt * 8 + 2 * cc;
                float m00 = silu_f(acc[mt][nt][0] + sxB2[n0]);
                float m01 = silu_f(acc[mt][nt][1] + sxB2[n0 + 1]);
                float m10 = silu_f(acc[mt][nt][2] + sxB2[n0]);
                float m11 = silu_f(acc[mt][nt][3] + sxB2[n0 + 1]);
                if (DO_MSG) {
                    REDV2(g_msg + (size_t)r0 * 64 + n0, m00, m01);
                    REDV2(g_msg + (size_t)r1 * 64 + n0, m10, m11);
                }
                if (DO_POS) {
                    const int word = nt * 4 + cc;
                    A_C[e0 * 36 + word] = pk2(m00, m01);
                    A_C[e1 * 36 + word] = pk2(m10, m11);
                }
            }
        }

        if (DO_POS) {
            __syncwarp();
            // ---- stage 3: p1_pre = msg @ PW1 ----
#pragma unroll
            for (int mt = 0; mt < 2; ++mt)
#pragma unroll
                for (int nt = 0; nt < 8; ++nt)
#pragma unroll
                    for (int i = 0; i < 4; ++i) acc[mt][nt][i] = 0.0f;
#pragma unroll
            for (int kt = 0; kt < 4; ++kt) stepK(acc, A_C, P1s, 36, 36, kt * 8, kt * 8, tb, g, cc);

            // ---- epilogue 3: w = silu(.+pb1) . pW2 + pb2; scatter diff*w ----
#pragma unroll
            for (int mt = 0; mt < 2; ++mt) {
                const int q0 = mt * 16 + g, q1 = q0 + 8;
                float w0 = 0.0f, w1 = 0.0f;
#pragma unroll
                for (int nt = 0; nt < 8; ++nt) {
                    const int n0 = nt * 8 + 2 * cc;
                    const float2 p0 = sxP[n0], p1 = sxP[n0 + 1];
                    w0 += silu_f(acc[mt][nt][0] + p0.x) * p0.y + silu_f(acc[mt][nt][1] + p1.x) * p1.y;
                    w1 += silu_f(acc[mt][nt][2] + p0.x) * p0.y + silu_f(acc[mt][nt][3] + p1.x) * p1.y;
                }
                w0 += __shfl_xor_sync(0xffffffffu, w0, 1);
                w0 += __shfl_xor_sync(0xffffffffu, w0, 2);
                w1 += __shfl_xor_sync(0xffffffffu, w1, 1);
                w1 += __shfl_xor_sync(0xffffffffu, w1, 2);
                const float dx0 = SHF(dx, q0), dy0 = SHF(dy, q0), dz0 = SHF(dz, q0);
                const float dx1 = SHF(dx, q1), dy1 = SHF(dy, q1), dz1 = SHF(dz, q1);
                if (cc == 0) {
                    const int r0 = r0s[mt], r1 = r1s[mt];
                    const float wa = w0 + pb2v, wb = w1 + pb2v;
                    atomicAdd(&g_pagg[r0 * 3 + 0], dx0 * wa);
                    atomicAdd(&g_pagg[r0 * 3 + 1], dy0 * wa);
                    atomicAdd(&g_pagg[r0 * 3 + 2], dz0 * wa);
                    atomicAdd(&g_pagg[r1 * 3 + 0], dx1 * wb);
                    atomicAdd(&g_pagg[r1 * 3 + 1], dy1 * wb);
                    atomicAdd(&g_pagg[r1 * 3 + 2], dz1 * wb);
                }
            }
        }
    }
}

// ================= node kernel (verbatim R3 structure: SIMT FFMA2, f32) =================
__device__ __forceinline__ ull fma2(ull a, ull b, ull c) {
    ull d;
    asm("fma.rn.f32x2 %0, %1, %2, %3;" : "=l"(d) : "l"(a), "l"(b), "l"(c));
    return d;
}
__device__ __forceinline__ ull pack2(float x) {
    ull r;
    asm("mov.b64 %0, {%1, %1};" : "=l"(r) : "f"(x));
    return r;
}
__device__ __forceinline__ float2 unpack2(ull v) {
    float2 f;
    asm("mov.b64 {%0, %1}, %2;" : "=f"(f.x), "=f"(f.y) : "l"(v));
    return f;
}
__device__ __forceinline__ void mac16(ull* acc, const ulonglong2* Wq, int krow, float x) {
    ull xx = pack2(x);
    const ulonglong2* wp = Wq + krow * 16;
#pragma unroll
    for (int jq = 0; jq < 16; ++jq) {
        ulonglong2 w = wp[jq];
        acc[2 * jq]     = fma2(xx, w.x, acc[2 * jq]);
        acc[2 * jq + 1] = fma2(xx, w.y, acc[2 * jq + 1]);
    }
}

#define N_SW1  0
#define N_SW2  8192
#define N_SB1  12288
#define N_SB2  12352
#define N_HBUF 12416
#define N_SMEMB ((12416 + 64 * NTPB) * 4)

template <bool DO_POS>
__global__ void __launch_bounds__(NTPB)
node_kernel(int featSel, int posSel,
            const float* __restrict__ W1, const float* __restrict__ b1,
            const float* __restrict__ W2, const float* __restrict__ b2)
{
    extern __shared__ float smf[];
    const int tid = threadIdx.x;
    for (int i = tid; i < 128 * 64; i += NTPB) smf[N_SW1 + i] = W1[i];
    for (int i = tid; i < 64 * 64; i += NTPB) smf[N_SW2 + i] = W2[i];
    if (tid < 64) { smf[N_SB1 + tid] = b1[tid]; smf[N_SB2 + tid] = b2[tid]; }
    __syncthreads();

    const float* featIn  = featSel ? g_featB : g_featA;
    float*       featOut = featSel ? g_featA : g_featB;
    const float* posIn   = posSel ? g_posB : g_posA;
    float*       posOut  = posSel ? g_posA : g_posB;
    const ulonglong2* W1q = (const ulonglong2*)(smf + N_SW1);
    const ulonglong2* W2q = (const ulonglong2*)(smf + N_SW2);
    const ull* B1q = (const ull*)(smf + N_SB1);
    const ull* B2q = (const ull*)(smf + N_SB2);
    float* hb = smf + N_HBUF + tid;

    for (int n = blockIdx.x * NTPB + tid; n < NN; n += gridDim.x * NTPB) {
        const float inv = g_inv[n];
        ull acc[32];
#pragma unroll
        for (int i = 0; i < 32; ++i) acc[i] = B1q[i];

        const float4* fr = (const float4*)(featIn + (size_t)n * 64);
#pragma unroll 2
        for (int q = 0; q < 16; ++q) {
            float4 v = fr[q];
            mac16(acc, W1q, 4 * q + 0, v.x);
            mac16(acc, W1q, 4 * q + 1, v.y);
            mac16(acc, W1q, 4 * q + 2, v.z);
            mac16(acc, W1q, 4 * q + 3, v.w);
        }
        float4* fm = (float4*)(g_msg + (size_t)n * 64);
#pragma unroll 2
        for (int q = 0; q < 16; ++q) {
            float4 v = fm[q];
            mac16(acc, W1q, 64 + 4 * q + 0, v.x * inv);
            mac16(acc, W1q, 64 + 4 * q + 1, v.y * inv);
            mac16(acc, W1q, 64 + 4 * q + 2, v.z * inv);
            mac16(acc, W1q, 64 + 4 * q + 3, v.w * inv);
        }
        const float4 z4 = make_float4(0.f, 0.f, 0.f, 0.f);
#pragma unroll
        for (int q = 0; q < 16; ++q) fm[q] = z4;   // zero msg for next layer

#pragma unroll
        for (int i = 0; i < 32; ++i) {
            float2 f = unpack2(acc[i]);
            hb[(2 * i) * NTPB]     = silu_f(f.x);
            hb[(2 * i + 1) * NTPB] = silu_f(f.y);
        }
#pragma unroll
        for (int i = 0; i < 32; ++i) acc[i] = B2q[i];
#pragma unroll 4
        for (int k = 0; k < 64; ++k) mac16(acc, W2q, k, hb[k * NTPB]);

        float* fo = featOut + (size_t)n * 64;
#pragma unroll
        for (int i = 0; i < 32; ++i) {
            float2 f = unpack2(acc[i]);
            fo[2 * i]     = f.x;
            fo[2 * i + 1] = f.y;
        }

        if (DO_POS) {
            posOut[n * 3 + 0] = posIn[n * 3 + 0] + g_pagg[n * 3 + 0] * inv;
            posOut[n * 3 + 1] = posIn[n * 3 + 1] + g_pagg[n * 3 + 1] * inv;
            posOut[n * 3 + 2] = posIn[n * 3 + 2] + g_pagg[n * 3 + 2] * inv;
        }
        g_pagg[n * 3 + 0] = 0.f;
        g_pagg[n * 3 + 1] = 0.f;
        g_pagg[n * 3 + 2] = 0.f;
    }
}

// ================= helper kernels =================
__global__ void init_kernel(const float* __restrict__ pos) {
    int i = blockIdx.x * blockDim.x + threadIdx.x;
    if (i < NN * 64) g_msg[i] = 0.0f;
    if (i < NN * 3) { g_pagg[i] = 0.0f; g_posB[i] = pos[i]; }
    if (i < NN) g_cnt[i] = 0;
}
__global__ void count_kernel(const int* __restrict__ row) {
    int e = blockIdx.x * blockDim.x + threadIdx.x;
    if (e < EE) atomicAdd(&g_cnt[row[e]], 1);
}
__global__ void prep_kernel(const float* __restrict__ nf, const float* __restrict__ embW,
                            const float* __restrict__ embb,
                            const float* __restrict__ mW1, const float* __restrict__ mW2,
                            const float* __restrict__ pW1) {
    int i = blockIdx.x * blockDim.x + threadIdx.x;
    if (i < NN) g_inv[i] = 1.0f / fmaxf((float)g_cnt[i], 1.0f);
    if (i < NN * 64) {
        int n = i >> 6, j = i & 63;
        g_featA[i] = nf[2 * n] * embW[j] + nf[2 * n + 1] * embW[64 + j] + embb[j];
    }
    if (i < 5 * 8192) {
        int l = i >> 13, rem = i & 8191;
        u32 out;
        if (rem < 4096) {                    // W1t: row n, word w -> (W1[2w][n], W1[2w+1][n])
            int n = rem >> 6, w = rem & 63;
            int k = 2 * w;
            out = pk2(mW1[l * 131 * 64 + k * 64 + n], mW1[l * 131 * 64 + (k + 1) * 64 + n]);
        } else {
            int rem2 = rem - 4096;
            int mat = rem2 >> 11, idx = rem2 & 2047;
            int n = idx >> 5, w = idx & 31;
            int k = 2 * w;
            const float* src = (mat == 0) ? mW2 : pW1;
            out = pk2(src[l * 4096 + k * 64 + n], src[l * 4096 + (k + 1) * 64 + n]);
        }
        g_wb[i] = out;
    }
}
__global__ void pos_final_kernel(float* __restrict__ out) {
    int i = blockIdx.x * blockDim.x + threadIdx.x;
    if (i < NN * 3) {
        int n = i / 3;
        out[i] = g_posA[i] + g_pagg[i] * g_inv[n];
    }
}

extern "C" void kernel_launch(void* const* d_in, const int* in_sizes, int n_in,
                              void* d_out, int out_size)
{
    const float*  node_feat = (const float*)d_in[0];
    const float*  node_pos  = (const float*)d_in[1];
    const float2* edge_attr = (const float2*)d_in[2];
    const int*    row       = (const int*)d_in[3];
    const int*    col       = (const int*)d_in[4];
    const float*  emb_W     = (const float*)d_in[5];
    const float*  emb_b     = (const float*)d_in[6];
    const float*  mW1 = (const float*)d_in[7];
    const float*  mb1 = (const float*)d_in[8];
    const float*  mW2 = (const float*)d_in[9];
    const float*  mb2 = (const float*)d_in[10];
    const float*  pW1 = (const float*)d_in[11];
    const float*  pb1 = (const float*)d_in[12];
    const float*  pW2 = (const float*)d_in[13];
    const float*  pb2 = (const float*)d_in[14];
    const float*  nW1 = (const float*)d_in[15];
    const float*  nb1 = (const float*)d_in[16];
    const float*  nW2 = (const float*)d_in[17];
    const float*  nb2 = (const float*)d_in[18];
    float* out = (float*)d_out;

    cudaFuncSetAttribute(edge_kernel<true, false>, cudaFuncAttributeMaxDynamicSharedMemorySize, SM_TOT);
    cudaFuncSetAttribute(edge_kernel<true, true>,  cudaFuncAttributeMaxDynamicSharedMemorySize, SM_TOT);
    cudaFuncSetAttribute(edge_kernel<false, true>, cudaFuncAttributeMaxDynamicSharedMemorySize, SM_TOT);
    cudaFuncSetAttribute(node_kernel<false>, cudaFuncAttributeMaxDynamicSharedMemorySize, N_SMEMB);
    cudaFuncSetAttribute(node_kernel<true>,  cudaFuncAttributeMaxDynamicSharedMemorySize, N_SMEMB);

    const int ZG = (NN * 64 + 255) / 256;

    init_kernel<<<ZG, 256>>>(node_pos);
    count_kernel<<<(EE + 255) / 256, 256>>>(row);
    prep_kernel<<<ZG, 256>>>(node_feat, emb_W, emb_b, mW1, mW2, pW1);

#define EDGE_ARGS(l) edge_attr, row, col, \
        mW1 + (l) * 131 * 64, mb1 + (l) * 64, mb2 + (l) * 64, \
        pb1 + (l) * 64, pW2 + (l) * 64, pb2 + (l)
#define NODE_ARGS(l) nW1 + (l) * 128 * 64, nb1 + (l) * 64, nW2 + (l) * 4096, nb2 + (l) * 64

    // L0 (com_node_feat_net): feat only
    edge_kernel<true, false><<<EGRID, ETPB, SM_TOT>>>(0, 1, 0, EDGE_ARGS(0));
    node_kernel<false><<<NGRID, NTPB, N_SMEMB>>>(0, 1, NODE_ARGS(0));
    // L1
    edge_kernel<true, true><<<EGRID, ETPB, SM_TOT>>>(1, 1, 1, EDGE_ARGS(1));
    node_kernel<true><<<NGRID, NTPB, N_SMEMB>>>(1, 1, NODE_ARGS(1));
    // L2
    edge_kernel<true, true><<<EGRID, ETPB, SM_TOT>>>(0, 0, 2, EDGE_ARGS(2));
    node_kernel<true><<<NGRID, NTPB, N_SMEMB>>>(0, 0, NODE_ARGS(2));
    // L3
    edge_kernel<true, true><<<EGRID, ETPB, SM_TOT>>>(1, 1, 3, EDGE_ARGS(3));
    node_kernel<true><<<NGRID, NTPB, N_SMEMB>>>(1, 1, NODE_ARGS(3));
    // L4: pos only
    edge_kernel<false, true><<<EGRID, ETPB, SM_TOT>>>(0, 0, 4, EDGE_ARGS(4));
    pos_final_kernel<<<(NN * 3 + 255) / 256, 256>>>(out);

#undef EDGE_ARGS
#undef NODE_ARGS
}

// round 9
// speedup vs baseline: 3.6744x; 1.2241x over previous
#include <cuda_runtime.h>
#include <cstdint>

#define NN 50000
#define EE 800000
#define ETPB 256
#define NTILES 3125        // EE / 256 exactly
#define EGRID 296
#define NTPB 128
#define NGRID 400

typedef unsigned long long ull;
typedef unsigned int u32;

// -------- persistent device scratch (f32 feat for node kernel; packed bf16 copy for edge) --------
__device__ float g_featA[NN * 64];
__device__ float g_featB[NN * 64];
__device__ u32   g_featP[NN * 32];   // bf16x2 words, word w = cols 2w,2w+1 (edge-gather copy)
__device__ float g_posA[NN * 3];
__device__ float g_posB[NN * 3];
__device__ float g_msg[NN * 64];
__device__ float g_pagg[NN * 3];
__device__ float g_inv[NN];
__device__ int   g_cnt[NN];
__device__ u32   g_wb[5 * 8192];  // per layer: W1t 64n x 64w, W2t 64n x 32w, P1t 64n x 32w (bf16x2 words, natural order)

// -------- helpers (no cuda_bf16.h) --------
__device__ __forceinline__ float silu_f(float x) {
    return x * __fdividef(1.0f, 1.0f + __expf(-x));
}
// pack two f32 -> bf16x2 word: lo -> low half (col 2w), hi -> high half (col 2w+1)
__device__ __forceinline__ u32 pk2(float lo, float hi) {
    u32 r;
    asm("cvt.rn.bf16x2.f32 %0, %1, %2;" : "=r"(r) : "f"(hi), "f"(lo));
    return r;
}

#define MMAB(d, a0, a1, a2, a3, b0, b1)                                            \
    asm volatile("mma.sync.aligned.m16n8k16.row.col.f32.bf16.bf16.f32 "            \
                 "{%0,%1,%2,%3}, {%4,%5,%6,%7}, {%8,%9}, {%0,%1,%2,%3};"           \
                 : "+f"((d)[0]), "+f"((d)[1]), "+f"((d)[2]), "+f"((d)[3])          \
                 : "r"(a0), "r"(a1), "r"(a2), "r"(a3), "r"(b0), "r"(b1))

#define REDV2(p, a, b)                                                             \
    asm volatile("red.global.add.v2.f32 [%0], {%1, %2};" :: "l"(p), "f"(a), "f"(b) : "memory")

#define SHF(v, src) __shfl_sync(0xffffffffu, (v), (src))

// -------- edge kernel SMEM layout (byte offsets), ETPB=256 (identical to R7) --------
#define O_W1   0
#define O_W2   17408
#define O_P1   26624
#define O_AR   35840
#define O_AC   72704
#define O_SXT  109568
#define O_SB2  110592
#define O_SXP  110848
#define SM_TOT 111360

// one k16 step: 16 MMAs; all fragments are single 32-bit shared words (natural k-pair order)
__device__ __forceinline__ void stepK(float acc[2][8][4], const u32* A, const u32* B,
                                      int Astride, int Bstride, int kwA, int kwB,
                                      int tb, int g, int cc)
{
    u32 b0[8], b1[8];
#pragma unroll
    for (int nt = 0; nt < 8; ++nt) {
        const u32* br = B + (nt * 8 + g) * Bstride + kwB;
        b0[nt] = br[cc];
        b1[nt] = br[4 + cc];
    }
#pragma unroll
    for (int mt = 0; mt < 2; ++mt) {
        const u32* ar = A + (tb + mt * 16 + g) * Astride + kwA;
        u32 a0 = ar[cc];
        u32 a1 = ar[8 * Astride + cc];
        u32 a2 = ar[4 + cc];
        u32 a3 = ar[8 * Astride + 4 + cc];
#pragma unroll
        for (int nt = 0; nt < 8; ++nt)
            MMAB(acc[mt][nt], a0, a1, a2, a3, b0[nt], b1[nt]);
    }
}

template <bool DO_MSG, bool DO_POS>
__global__ void __launch_bounds__(ETPB)
edge_kernel(int posSel, int layer,
            const float2* __restrict__ ea_g,
            const int* __restrict__ row, const int* __restrict__ col,
            const float* __restrict__ mW1, const float* __restrict__ mb1,
            const float* __restrict__ mb2, const float* __restrict__ pb1,
            const float* __restrict__ pW2, const float* __restrict__ pb2)
{
    extern __shared__ __align__(16) char sm[];
    u32*    W1s  = (u32*)(sm + O_W1);
    u32*    W2s  = (u32*)(sm + O_W2);
    u32*    P1s  = (u32*)(sm + O_P1);
    u32*    A_R  = (u32*)(sm + O_AR);
    u32*    A_C  = (u32*)(sm + O_AC);
    float4* sxT  = (float4*)(sm + O_SXT);
    float*  sxB2 = (float*)(sm + O_SB2);
    float2* sxP  = (float2*)(sm + O_SXP);

    const int tid = threadIdx.x;

    // ---- stage weights (bf16x2 words) ----
    {
        const u32* wsrc = g_wb + layer * 8192;
        for (int i = tid; i < 4096; i += ETPB) {
            int n = i >> 6, w = i & 63;
            W1s[n * 68 + w] = wsrc[i];
        }
        for (int i = tid; i < 2048; i += ETPB) {
            int n = i >> 5, w = i & 31;
            W2s[n * 36 + w] = wsrc[4096 + i];
            P1s[n * 36 + w] = wsrc[6144 + i];
        }
    }
    if (tid < 64) {
        sxT[tid] = make_float4(mW1[128 * 64 + tid], mW1[129 * 64 + tid], mW1[130 * 64 + tid], mb1[tid]);
        sxB2[tid] = mb2[tid];
        sxP[tid] = make_float2(pb1[tid], pW2[tid]);
    }
    const float pb2v = pb2[0];
    __syncthreads();

    const float* posIn = posSel ? g_posB : g_posA;

    const int lane = tid & 31;
    const int g  = lane >> 2;
    const int cc = lane & 3;
    const int tb = (tid >> 5) * 32;

    for (int tile = blockIdx.x; tile < NTILES; tile += gridDim.x) {
        __syncwarp();
        // ---- prologue: per-thread edge (values stay in registers; shuffled later) ----
        const int e = tile * ETPB + tid;
        const int r = row[e], c = col[e];
        const float dx = posIn[r * 3 + 0] - posIn[c * 3 + 0];
        const float dy = posIn[r * 3 + 1] - posIn[c * 3 + 1];
        const float dz = posIn[r * 3 + 2] - posIn[c * 3 + 2];
        const float dist = dx * dx + dy * dy + dz * dz;
        const float2 ea = ea_g[e];

        // gather feat rows: raw bf16x2 copy (8 LDG.128 + 8 STS.128 per row)
        {
            const uint4* fr4 = (const uint4*)(g_featP + (size_t)r * 32);
            const uint4* fc4 = (const uint4*)(g_featP + (size_t)c * 32);
            u32* aR = A_R + tid * 36;
            u32* aC = A_C + tid * 36;
#pragma unroll
            for (int q = 0; q < 8; ++q) {
                *(uint4*)(aR + 4 * q) = fr4[q];
                *(uint4*)(aC + 4 * q) = fc4[q];
            }
        }
        __syncwarp();

        float acc[2][8][4];
#pragma unroll
        for (int mt = 0; mt < 2; ++mt)
#pragma unroll
            for (int nt = 0; nt < 8; ++nt)
#pragma unroll
                for (int i = 0; i < 4; ++i) acc[mt][nt][i] = 0.0f;

        // ---- stage 1: h1_pre = featR @ W1[0:64] + featC @ W1[64:128] ----
#pragma unroll
        for (int kt = 0; kt < 4; ++kt) stepK(acc, A_R, W1s, 36, 68, kt * 8, kt * 8, tb, g, cc);
#pragma unroll
        for (int kt = 0; kt < 4; ++kt) stepK(acc, A_C, W1s, 36, 68, kt * 8, 32 + kt * 8, tb, g, cc);

        // ---- epilogue 1: tail (ea, dist, b1) + silu -> h1 (bf16 words) into A_R ----
#pragma unroll
        for (int mt = 0; mt < 2; ++mt) {
            const int q0 = mt * 16 + g, q1 = q0 + 8;     // warp-local rows
            const float ex0 = SHF(ea.x, q0), ey0 = SHF(ea.y, q0), ds0 = SHF(dist, q0);
            const float ex1 = SHF(ea.x, q1), ey1 = SHF(ea.y, q1), ds1 = SHF(dist, q1);
            const int e0 = tb + q0, e1 = tb + q1;
#pragma unroll
            for (int nt = 0; nt < 8; ++nt) {
                const int n0 = nt * 8 + 2 * cc;
                const float4 t0 = sxT[n0], t1 = sxT[n0 + 1];
                float v00 = silu_f(acc[mt][nt][0] + t0.w + ex0 * t0.x + ey0 * t0.y + ds0 * t0.z);
                float v01 = silu_f(acc[mt][nt][1] + t1.w + ex0 * t1.x + ey0 * t1.y + ds0 * t1.z);
                float v10 = silu_f(acc[mt][nt][2] + t0.w + ex1 * t0.x + ey1 * t0.y + ds1 * t0.z);
                float v11 = silu_f(acc[mt][nt][3] + t1.w + ex1 * t1.x + ey1 * t1.y + ds1 * t1.z);
                const int word = nt * 4 + cc;
                A_R[e0 * 36 + word] = pk2(v00, v01);
                A_R[e1 * 36 + word] = pk2(v10, v11);
            }
        }
        __syncwarp();

        // ---- stage 2: msg_pre = h1 @ W2 ----
#pragma unroll
        for (int mt = 0; mt < 2; ++mt)
#pragma unroll
            for (int nt = 0; nt < 8; ++nt)
#pragma unroll
                for (int i = 0; i < 4; ++i) acc[mt][nt][i] = 0.0f;
#pragma unroll
        for (int kt = 0; kt < 4; ++kt) stepK(acc, A_R, W2s, 36, 36, kt * 8, kt * 8, tb, g, cc);

        // ---- epilogue 2: silu -> msg; red.v2 scatter; msg (bf16) -> A_C ----
        int r0s[2], r1s[2];
#pragma unroll
        for (int mt = 0; mt < 2; ++mt) {
            const int q0 = mt * 16 + g, q1 = q0 + 8;
            const int r0 = SHF(r, q0), r1 = SHF(r, q1);
            r0s[mt] = r0; r1s[mt] = r1;
            const int e0 = tb + q0, e1 = tb + q1;
#pragma unroll
            for (int nt = 0; nt < 8; ++nt) {
                const int n0 = nt * 8 + 2 * cc;
                float m00 = silu_f(acc[mt][nt][0] + sxB2[n0]);
                float m01 = silu_f(acc[mt][nt][1] + sxB2[n0 + 1]);
                float m10 = silu_f(acc[mt][nt][2] + sxB2[n0]);
                float m11 = silu_f(acc[mt][nt][3] + sxB2[n0 + 1]);
                if (DO_MSG) {
                    REDV2(g_msg + (size_t)r0 * 64 + n0, m00, m01);
                    REDV2(g_msg + (size_t)r1 * 64 + n0, m10, m11);
                }
                if (DO_POS) {
                    const int word = nt * 4 + cc;
                    A_C[e0 * 36 + word] = pk2(m00, m01);
                    A_C[e1 * 36 + word] = pk2(m10, m11);
                }
            }
        }

        if (DO_POS) {
            __syncwarp();
            // ---- stage 3: p1_pre = msg @ PW1 ----
#pragma unroll
            for (int mt = 0; mt < 2; ++mt)
#pragma unroll
                for (int nt = 0; nt < 8; ++nt)
#pragma unroll
                    for (int i = 0; i < 4; ++i) acc[mt][nt][i] = 0.0f;
#pragma unroll
            for (int kt = 0; kt < 4; ++kt) stepK(acc, A_C, P1s, 36, 36, kt * 8, kt * 8, tb, g, cc);

            // ---- epilogue 3: w = silu(.+pb1) . pW2 + pb2; scatter diff*w ----
#pragma unroll
            for (int mt = 0; mt < 2; ++mt) {
                const int q0 = mt * 16 + g, q1 = q0 + 8;
                float w0 = 0.0f, w1 = 0.0f;
#pragma unroll
                for (int nt = 0; nt < 8; ++nt) {
                    const int n0 = nt * 8 + 2 * cc;
                    const float2 p0 = sxP[n0], p1 = sxP[n0 + 1];
                    w0 += silu_f(acc[mt][nt][0] + p0.x) * p0.y + silu_f(acc[mt][nt][1] + p1.x) * p1.y;
                    w1 += silu_f(acc[mt][nt][2] + p0.x) * p0.y + silu_f(acc[mt][nt][3] + p1.x) * p1.y;
                }
                w0 += __shfl_xor_sync(0xffffffffu, w0, 1);
                w0 += __shfl_xor_sync(0xffffffffu, w0, 2);
                w1 += __shfl_xor_sync(0xffffffffu, w1, 1);
                w1 += __shfl_xor_sync(0xffffffffu, w1, 2);
                const float dx0 = SHF(dx, q0), dy0 = SHF(dy, q0), dz0 = SHF(dz, q0);
                const float dx1 = SHF(dx, q1), dy1 = SHF(dy, q1), dz1 = SHF(dz, q1);
                if (cc == 0) {
                    const int r0 = r0s[mt], r1 = r1s[mt];
                    const float wa = w0 + pb2v, wb = w1 + pb2v;
                    atomicAdd(&g_pagg[r0 * 3 + 0], dx0 * wa);
                    atomicAdd(&g_pagg[r0 * 3 + 1], dy0 * wa);
                    atomicAdd(&g_pagg[r0 * 3 + 2], dz0 * wa);
                    atomicAdd(&g_pagg[r1 * 3 + 0], dx1 * wb);
                    atomicAdd(&g_pagg[r1 * 3 + 1], dy1 * wb);
                    atomicAdd(&g_pagg[r1 * 3 + 2], dz1 * wb);
                }
            }
        }
    }
}

// ================= node kernel (VERBATIM R7: SIMT FFMA2, f32 feat I/O) =================
__device__ __forceinline__ ull fma2(ull a, ull b, ull c) {
    ull d;
    asm("fma.rn.f32x2 %0, %1, %2, %3;" : "=l"(d) : "l"(a), "l"(b), "l"(c));
    return d;
}
__device__ __forceinline__ ull pack2(float x) {
    ull r;
    asm("mov.b64 %0, {%1, %1};" : "=l"(r) : "f"(x));
    return r;
}
__device__ __forceinline__ float2 unpack2(ull v) {
    float2 f;
    asm("mov.b64 {%0, %1}, %2;" : "=f"(f.x), "=f"(f.y) : "l"(v));
    return f;
}
__device__ __forceinline__ void mac16(ull* acc, const ulonglong2* Wq, int krow, float x) {
    ull xx = pack2(x);
    const ulonglong2* wp = Wq + krow * 16;
#pragma unroll
    for (int jq = 0; jq < 16; ++jq) {
        ulonglong2 w = wp[jq];
        acc[2 * jq]     = fma2(xx, w.x, acc[2 * jq]);
        acc[2 * jq + 1] = fma2(xx, w.y, acc[2 * jq + 1]);
    }
}

#define N_SW1  0
#define N_SW2  8192
#define N_SB1  12288
#define N_SB2  12352
#define N_HBUF 12416
#define N_SMEMB ((12416 + 64 * NTPB) * 4)

template <bool DO_POS>
__global__ void __launch_bounds__(NTPB)
node_kernel(int featSel, int posSel,
            const float* __restrict__ W1, const float* __restrict__ b1,
            const float* __restrict__ W2, const float* __restrict__ b2)
{
    extern __shared__ float smf[];
    const int tid = threadIdx.x;
    for (int i = tid; i < 128 * 64; i += NTPB) smf[N_SW1 + i] = W1[i];
    for (int i = tid; i < 64 * 64; i += NTPB) smf[N_SW2 + i] = W2[i];
    if (tid < 64) { smf[N_SB1 + tid] = b1[tid]; smf[N_SB2 + tid] = b2[tid]; }
    __syncthreads();

    const float* featIn  = featSel ? g_featB : g_featA;
    float*       featOut = featSel ? g_featA : g_featB;
    const float* posIn   = posSel ? g_posB : g_posA;
    float*       posOut  = posSel ? g_posA : g_posB;
    const ulonglong2* W1q = (const ulonglong2*)(smf + N_SW1);
    const ulonglong2* W2q = (const ulonglong2*)(smf + N_SW2);
    const ull* B1q = (const ull*)(smf + N_SB1);
    const ull* B2q = (const ull*)(smf + N_SB2);
    float* hb = smf + N_HBUF + tid;

    for (int n = blockIdx.x * NTPB + tid; n < NN; n += gridDim.x * NTPB) {
        const float inv = g_inv[n];
        ull acc[32];
#pragma unroll
        for (int i = 0; i < 32; ++i) acc[i] = B1q[i];

        const float4* fr = (const float4*)(featIn + (size_t)n * 64);
#pragma unroll 2
        for (int q = 0; q < 16; ++q) {
            float4 v = fr[q];
            mac16(acc, W1q, 4 * q + 0, v.x);
            mac16(acc, W1q, 4 * q + 1, v.y);
            mac16(acc, W1q, 4 * q + 2, v.z);
            mac16(acc, W1q, 4 * q + 3, v.w);
        }
        float4* fm = (float4*)(g_msg + (size_t)n * 64);
#pragma unroll 2
        for (int q = 0; q < 16; ++q) {
            float4 v = fm[q];
            mac16(acc, W1q, 64 + 4 * q + 0, v.x * inv);
            mac16(acc, W1q, 64 + 4 * q + 1, v.y * inv);
            mac16(acc, W1q, 64 + 4 * q + 2, v.z * inv);
            mac16(acc, W1q, 64 + 4 * q + 3, v.w * inv);
        }
        const float4 z4 = make_float4(0.f, 0.f, 0.f, 0.f);
#pragma unroll
        for (int q = 0; q < 16; ++q) fm[q] = z4;   // zero msg for next layer

#pragma unroll
        for (int i = 0; i < 32; ++i) {
            float2 f = unpack2(acc[i]);
            hb[(2 * i) * NTPB]     = silu_f(f.x);
            hb[(2 * i + 1) * NTPB] = silu_f(f.y);
        }
#pragma unroll
        for (int i = 0; i < 32; ++i) acc[i] = B2q[i];
#pragma unroll 4
        for (int k = 0; k < 64; ++k) mac16(acc, W2q, k, hb[k * NTPB]);

        float* fo = featOut + (size_t)n * 64;
#pragma unroll
        for (int i = 0; i < 32; ++i) {
            float2 f = unpack2(acc[i]);
            fo[2 * i]     = f.x;
            fo[2 * i + 1] = f.y;
        }

        if (DO_POS) {
            posOut[n * 3 + 0] = posIn[n * 3 + 0] + g_pagg[n * 3 + 0] * inv;
            posOut[n * 3 + 1] = posIn[n * 3 + 1] + g_pagg[n * 3 + 1] * inv;
            posOut[n * 3 + 2] = posIn[n * 3 + 2] + g_pagg[n * 3 + 2] * inv;
        }
        g_pagg[n * 3 + 0] = 0.f;
        g_pagg[n * 3 + 1] = 0.f;
        g_pagg[n * 3 + 2] = 0.f;
    }
}

// ================= helper kernels =================
__global__ void init_kernel(const float* __restrict__ pos) {
    int i = blockIdx.x * blockDim.x + threadIdx.x;
    if (i < NN * 64) g_msg[i] = 0.0f;
    if (i < NN * 3) { g_pagg[i] = 0.0f; g_posB[i] = pos[i]; }
    if (i < NN) g_cnt[i] = 0;
}
__global__ void count_kernel(const int* __restrict__ row) {
    int e = blockIdx.x * blockDim.x + threadIdx.x;
    if (e < EE) atomicAdd(&g_cnt[row[e]], 1);
}
// dedicated feat packer: f32 feat row -> bf16x2 words (trivially spill-free)
__global__ void pack_kernel(int featSel) {
    int i = blockIdx.x * blockDim.x + threadIdx.x;
    if (i < NN * 32) {
        const float* src = featSel ? g_featB : g_featA;
        g_featP[i] = pk2(src[2 * i], src[2 * i + 1]);
    }
}
__global__ void prep_kernel(const float* __restrict__ nf, const float* __restrict__ embW,
                            const float* __restrict__ embb,
                            const float* __restrict__ mW1, const float* __restrict__ mW2,
                            const float* __restrict__ pW1) {
    int i = blockIdx.x * blockDim.x + threadIdx.x;
    if (i < NN) g_inv[i] = 1.0f / fmaxf((float)g_cnt[i], 1.0f);
    if (i < NN * 64) {
        int n = i >> 6, j = i & 63;
        g_featA[i] = nf[2 * n] * embW[j] + nf[2 * n + 1] * embW[64 + j] + embb[j];
    }
    if (i < 5 * 8192) {
        int l = i >> 13, rem = i & 8191;
        u32 out;
        if (rem < 4096) {                    // W1t: row n, word w -> (W1[2w][n], W1[2w+1][n])
            int n = rem >> 6, w = rem & 63;
            int k = 2 * w;
            out = pk2(mW1[l * 131 * 64 + k * 64 + n], mW1[l * 131 * 64 + (k + 1) * 64 + n]);
        } else {
            int rem2 = rem - 4096;
            int mat = rem2 >> 11, idx = rem2 & 2047;
            int n = idx >> 5, w = idx & 31;
            int k = 2 * w;
            const float* src = (mat == 0) ? mW2 : pW1;
            out = pk2(src[l * 4096 + k * 64 + n], src[l * 4096 + (k + 1) * 64 + n]);
        }
        g_wb[i] = out;
    }
}
__global__ void pos_final_kernel(float* __restrict__ out) {
    int i = blockIdx.x * blockDim.x + threadIdx.x;
    if (i < NN * 3) {
        int n = i / 3;
        out[i] = g_posA[i] + g_pagg[i] * g_inv[n];
    }
}

extern "C" void kernel_launch(void* const* d_in, const int* in_sizes, int n_in,
                              void* d_out, int out_size)
{
    const float*  node_feat = (const float*)d_in[0];
    const float*  node_pos  = (const float*)d_in[1];
    const float2* edge_attr = (const float2*)d_in[2];
    const int*    row       = (const int*)d_in[3];
    const int*    col       = (const int*)d_in[4];
    const float*  emb_W     = (const float*)d_in[5];
    const float*  emb_b     = (const float*)d_in[6];
    const float*  mW1 = (const float*)d_in[7];
    const float*  mb1 = (const float*)d_in[8];
    const float*  mW2 = (const float*)d_in[9];
    const float*  mb2 = (const float*)d_in[10];
    const float*  pW1 = (const float*)d_in[11];
    const float*  pb1 = (const float*)d_in[12];
    const float*  pW2 = (const float*)d_in[13];
    const float*  pb2 = (const float*)d_in[14];
    const float*  nW1 = (const float*)d_in[15];
    const float*  nb1 = (const float*)d_in[16];
    const float*  nW2 = (const float*)d_in[17];
    const float*  nb2 = (const float*)d_in[18];
    float* out = (float*)d_out;

    cudaFuncSetAttribute(edge_kernel<true, false>, cudaFuncAttributeMaxDynamicSharedMemorySize, SM_TOT);
    cudaFuncSetAttribute(edge_kernel<true, true>,  cudaFuncAttributeMaxDynamicSharedMemorySize, SM_TOT);
    cudaFuncSetAttribute(edge_kernel<false, true>, cudaFuncAttributeMaxDynamicSharedMemorySize, SM_TOT);
    cudaFuncSetAttribute(node_kernel<false>, cudaFuncAttributeMaxDynamicSharedMemorySize, N_SMEMB);
    cudaFuncSetAttribute(node_kernel<true>,  cudaFuncAttributeMaxDynamicSharedMemorySize, N_SMEMB);

    const int ZG = (NN * 64 + 255) / 256;
    const int KG = (NN * 32 + 255) / 256;

    init_kernel<<<ZG, 256>>>(node_pos);
    count_kernel<<<(EE + 255) / 256, 256>>>(row);
    prep_kernel<<<ZG, 256>>>(node_feat, emb_W, emb_b, mW1, mW2, pW1);
    pack_kernel<<<KG, 256>>>(0);

#define EDGE_ARGS(l) edge_attr, row, col, \
        mW1 + (l) * 131 * 64, mb1 + (l) * 64, mb2 + (l) * 64, \
        pb1 + (l) * 64, pW2 + (l) * 64, pb2 + (l)
#define NODE_ARGS(l) nW1 + (l) * 128 * 64, nb1 + (l) * 64, nW2 + (l) * 4096, nb2 + (l) * 64

    // L0 (com_node_feat_net): feat only
    edge_kernel<true, false><<<EGRID, ETPB, SM_TOT>>>(1, 0, EDGE_ARGS(0));
    node_kernel<false><<<NGRID, NTPB, N_SMEMB>>>(0, 1, NODE_ARGS(0));
    pack_kernel<<<KG, 256>>>(1);
    // L1
    edge_kernel<true, true><<<EGRID, ETPB, SM_TOT>>>(1, 1, EDGE_ARGS(1));
    node_kernel<true><<<NGRID, NTPB, N_SMEMB>>>(1, 1, NODE_ARGS(1));
    pack_kernel<<<KG, 256>>>(0);
    // L2
    edge_kernel<true, true><<<EGRID, ETPB, SM_TOT>>>(0, 2, EDGE_ARGS(2));
    node_kernel<true><<<NGRID, NTPB, N_SMEMB>>>(0, 0, NODE_ARGS(2));
    pack_kernel<<<KG, 256>>>(1);
    // L3
    edge_kernel<true, true><<<EGRID, ETPB, SM_TOT>>>(1, 3, EDGE_ARGS(3));
    node_kernel<true><<<NGRID, NTPB, N_SMEMB>>>(1, 1, NODE_ARGS(3));
    pack_kernel<<<KG, 256>>>(0);
    // L4: pos only
    edge_kernel<false, true><<<EGRID, ETPB, SM_TOT>>>(0, 4, EDGE_ARGS(4));
    pos_final_kernel<<<(NN * 3 + 255) / 256, 256>>>(out);

#undef EDGE_ARGS
#undef NODE_ARGS
}

// round 10
// speedup vs baseline: 4.4631x; 1.2147x over previous
#include <cuda_runtime.h>
#include <cstdint>

#define NN 50000
#define EE 800000
#define ETPB 256
#define NTILES 3125        // EE / 256 exactly
#define EGRID 296
#define NTTILES 196        // ceil(NN / 256)

typedef unsigned long long ull;
typedef unsigned int u32;

// -------- persistent device scratch (feat = packed bf16x2 words only; NO cuda_bf16.h) --------
__device__ u32   g_featPA[NN * 32];
__device__ u32   g_featPB[NN * 32];
__device__ float g_posA[NN * 3];
__device__ float g_posB[NN * 3];
__device__ float g_msg[NN * 64];
__device__ float g_pagg[NN * 3];
__device__ float g_inv[NN];
__device__ int   g_cnt[NN];
__device__ u32   g_wb[5 * 8192];   // edge weights: W1t 64n x 64w, W2t 64n x 32w, P1t 64n x 32w
__device__ u32   g_wnb[5 * 6144];  // node weights: nW1t 64n x 64w, nW2t 64n x 32w

// -------- helpers --------
__device__ __forceinline__ float silu_f(float x) {
    return x * __fdividef(1.0f, 1.0f + __expf(-x));
}
__device__ __forceinline__ u32 pk2(float lo, float hi) {
    u32 r;
    asm("cvt.rn.bf16x2.f32 %0, %1, %2;" : "=r"(r) : "f"(hi), "f"(lo));
    return r;
}

#define MMAB(d, a0, a1, a2, a3, b0, b1)                                            \
    asm volatile("mma.sync.aligned.m16n8k16.row.col.f32.bf16.bf16.f32 "            \
                 "{%0,%1,%2,%3}, {%4,%5,%6,%7}, {%8,%9}, {%0,%1,%2,%3};"           \
                 : "+f"((d)[0]), "+f"((d)[1]), "+f"((d)[2]), "+f"((d)[3])          \
                 : "r"(a0), "r"(a1), "r"(a2), "r"(a3), "r"(b0), "r"(b1))

#define REDV2(p, a, b)                                                             \
    asm volatile("red.global.add.v2.f32 [%0], {%1, %2};" :: "l"(p), "f"(a), "f"(b) : "memory")

#define SHF(v, src) __shfl_sync(0xffffffffu, (v), (src))

// one k16 step: 16 MMAs; all fragments are single 32-bit shared words (natural k-pair order)
__device__ __forceinline__ void stepK(float acc[2][8][4], const u32* A, const u32* B,
                                      int Astride, int Bstride, int kwA, int kwB,
                                      int tb, int g, int cc)
{
    u32 b0[8], b1[8];
#pragma unroll
    for (int nt = 0; nt < 8; ++nt) {
        const u32* br = B + (nt * 8 + g) * Bstride + kwB;
        b0[nt] = br[cc];
        b1[nt] = br[4 + cc];
    }
#pragma unroll
    for (int mt = 0; mt < 2; ++mt) {
        const u32* ar = A + (tb + mt * 16 + g) * Astride + kwA;
        u32 a0 = ar[cc];
        u32 a1 = ar[8 * Astride + cc];
        u32 a2 = ar[4 + cc];
        u32 a3 = ar[8 * Astride + 4 + cc];
#pragma unroll
        for (int nt = 0; nt < 8; ++nt)
            MMAB(acc[mt][nt], a0, a1, a2, a3, b0[nt], b1[nt]);
    }
}

// -------- edge kernel SMEM layout (identical to R9) --------
#define O_W1   0
#define O_W2   17408
#define O_P1   26624
#define O_AR   35840
#define O_AC   72704
#define O_SXT  109568
#define O_SB2  110592
#define O_SXP  110848
#define SM_TOT 111360

template <bool DO_MSG, bool DO_POS>
__global__ void __launch_bounds__(ETPB)
edge_kernel(int featSel, int posSel, int layer,
            const float2* __restrict__ ea_g,
            const int* __restrict__ row, const int* __restrict__ col,
            const float* __restrict__ mW1, const float* __restrict__ mb1,
            const float* __restrict__ mb2, const float* __restrict__ pb1,
            const float* __restrict__ pW2, const float* __restrict__ pb2)
{
    extern __shared__ __align__(16) char sm[];
    u32*    W1s  = (u32*)(sm + O_W1);
    u32*    W2s  = (u32*)(sm + O_W2);
    u32*    P1s  = (u32*)(sm + O_P1);
    u32*    A_R  = (u32*)(sm + O_AR);
    u32*    A_C  = (u32*)(sm + O_AC);
    float4* sxT  = (float4*)(sm + O_SXT);
    float*  sxB2 = (float*)(sm + O_SB2);
    float2* sxP  = (float2*)(sm + O_SXP);

    const int tid = threadIdx.x;

    {
        const u32* wsrc = g_wb + layer * 8192;
        for (int i = tid; i < 4096; i += ETPB) {
            int n = i >> 6, w = i & 63;
            W1s[n * 68 + w] = wsrc[i];
        }
        for (int i = tid; i < 2048; i += ETPB) {
            int n = i >> 5, w = i & 31;
            W2s[n * 36 + w] = wsrc[4096 + i];
            P1s[n * 36 + w] = wsrc[6144 + i];
        }
    }
    if (tid < 64) {
        sxT[tid] = make_float4(mW1[128 * 64 + tid], mW1[129 * 64 + tid], mW1[130 * 64 + tid], mb1[tid]);
        sxB2[tid] = mb2[tid];
        sxP[tid] = make_float2(pb1[tid], pW2[tid]);
    }
    const float pb2v = pb2[0];
    __syncthreads();

    const u32* featP = featSel ? g_featPB : g_featPA;
    const float* posIn = posSel ? g_posB : g_posA;

    const int lane = tid & 31;
    const int g  = lane >> 2;
    const int cc = lane & 3;
    const int tb = (tid >> 5) * 32;

    for (int tile = blockIdx.x; tile < NTILES; tile += gridDim.x) {
        __syncwarp();
        const int e = tile * ETPB + tid;
        const int r = row[e], c = col[e];
        const float dx = posIn[r * 3 + 0] - posIn[c * 3 + 0];
        const float dy = posIn[r * 3 + 1] - posIn[c * 3 + 1];
        const float dz = posIn[r * 3 + 2] - posIn[c * 3 + 2];
        const float dist = dx * dx + dy * dy + dz * dz;
        const float2 ea = ea_g[e];

        // gather feat rows: raw bf16x2 copy
        {
            const uint4* fr4 = (const uint4*)(featP + (size_t)r * 32);
            const uint4* fc4 = (const uint4*)(featP + (size_t)c * 32);
            u32* aR = A_R + tid * 36;
            u32* aC = A_C + tid * 36;
#pragma unroll
            for (int q = 0; q < 8; ++q) {
                *(uint4*)(aR + 4 * q) = fr4[q];
                *(uint4*)(aC + 4 * q) = fc4[q];
            }
        }
        __syncwarp();

        float acc[2][8][4];
#pragma unroll
        for (int mt = 0; mt < 2; ++mt)
#pragma unroll
            for (int nt = 0; nt < 8; ++nt)
#pragma unroll
                for (int i = 0; i < 4; ++i) acc[mt][nt][i] = 0.0f;

        // ---- stage 1 ----
#pragma unroll
        for (int kt = 0; kt < 4; ++kt) stepK(acc, A_R, W1s, 36, 68, kt * 8, kt * 8, tb, g, cc);
#pragma unroll
        for (int kt = 0; kt < 4; ++kt) stepK(acc, A_C, W1s, 36, 68, kt * 8, 32 + kt * 8, tb, g, cc);

        // ---- epilogue 1 ----
#pragma unroll
        for (int mt = 0; mt < 2; ++mt) {
            const int q0 = mt * 16 + g, q1 = q0 + 8;
            const float ex0 = SHF(ea.x, q0), ey0 = SHF(ea.y, q0), ds0 = SHF(dist, q0);
            const float ex1 = SHF(ea.x, q1), ey1 = SHF(ea.y, q1), ds1 = SHF(dist, q1);
            const int e0 = tb + q0, e1 = tb + q1;
#pragma unroll
            for (int nt = 0; nt < 8; ++nt) {
                const int n0 = nt * 8 + 2 * cc;
                const float4 t0 = sxT[n0], t1 = sxT[n0 + 1];
                float v00 = silu_f(acc[mt][nt][0] + t0.w + ex0 * t0.x + ey0 * t0.y + ds0 * t0.z);
                float v01 = silu_f(acc[mt][nt][1] + t1.w + ex0 * t1.x + ey0 * t1.y + ds0 * t1.z);
                float v10 = silu_f(acc[mt][nt][2] + t0.w + ex1 * t0.x + ey1 * t0.y + ds1 * t0.z);
                float v11 = silu_f(acc[mt][nt][3] + t1.w + ex1 * t1.x + ey1 * t1.y + ds1 * t1.z);
                const int word = nt * 4 + cc;
                A_R[e0 * 36 + word] = pk2(v00, v01);
                A_R[e1 * 36 + word] = pk2(v10, v11);
            }
        }
        __syncwarp();

        // ---- stage 2 ----
#pragma unroll
        for (int mt = 0; mt < 2; ++mt)
#pragma unroll
            for (int nt = 0; nt < 8; ++nt)
#pragma unroll
                for (int i = 0; i < 4; ++i) acc[mt][nt][i] = 0.0f;
#pragma unroll
        for (int kt = 0; kt < 4; ++kt) stepK(acc, A_R, W2s, 36, 36, kt * 8, kt * 8, tb, g, cc);

        // ---- epilogue 2 ----
        int r0s[2], r1s[2];
#pragma unroll
        for (int mt = 0; mt < 2; ++mt) {
            const int q0 = mt * 16 + g, q1 = q0 + 8;
            const int r0 = SHF(r, q0), r1 = SHF(r, q1);
            r0s[mt] = r0; r1s[mt] = r1;
            const int e0 = tb + q0, e1 = tb + q1;
#pragma unroll
            for (int nt = 0; nt < 8; ++nt) {
                const int n0 = nt * 8 + 2 * cc;
                float m00 = silu_f(acc[mt][nt][0] + sxB2[n0]);
                float m01 = silu_f(acc[mt][nt][1] + sxB2[n0 + 1]);
                float m10 = silu_f(acc[mt][nt][2] + sxB2[n0]);
                float m11 = silu_f(acc[mt][nt][3] + sxB2[n0 + 1]);
                if (DO_MSG) {
                    REDV2(g_msg + (size_t)r0 * 64 + n0, m00, m01);
                    REDV2(g_msg + (size_t)r1 * 64 + n0, m10, m11);
                }
                if (DO_POS) {
                    const int word = nt * 4 + cc;
                    A_C[e0 * 36 + word] = pk2(m00, m01);
                    A_C[e1 * 36 + word] = pk2(m10, m11);
                }
            }
        }

        if (DO_POS) {
            __syncwarp();
            // ---- stage 3 ----
#pragma unroll
            for (int mt = 0; mt < 2; ++mt)
#pragma unroll
                for (int nt = 0; nt < 8; ++nt)
#pragma unroll
                    for (int i = 0; i < 4; ++i) acc[mt][nt][i] = 0.0f;
#pragma unroll
            for (int kt = 0; kt < 4; ++kt) stepK(acc, A_C, P1s, 36, 36, kt * 8, kt * 8, tb, g, cc);

            // ---- epilogue 3 ----
#pragma unroll
            for (int mt = 0; mt < 2; ++mt) {
                const int q0 = mt * 16 + g, q1 = q0 + 8;
                float w0 = 0.0f, w1 = 0.0f;
#pragma unroll
                for (int nt = 0; nt < 8; ++nt) {
                    const int n0 = nt * 8 + 2 * cc;
                    const float2 p0 = sxP[n0], p1 = sxP[n0 + 1];
                    w0 += silu_f(acc[mt][nt][0] + p0.x) * p0.y + silu_f(acc[mt][nt][1] + p1.x) * p1.y;
                    w1 += silu_f(acc[mt][nt][2] + p0.x) * p0.y + silu_f(acc[mt][nt][3] + p1.x) * p1.y;
                }
                w0 += __shfl_xor_sync(0xffffffffu, w0, 1);
                w0 += __shfl_xor_sync(0xffffffffu, w0, 2);
                w1 += __shfl_xor_sync(0xffffffffu, w1, 1);
                w1 += __shfl_xor_sync(0xffffffffu, w1, 2);
                const float dx0 = SHF(dx, q0), dy0 = SHF(dy, q0), dz0 = SHF(dz, q0);
                const float dx1 = SHF(dx, q1), dy1 = SHF(dy, q1), dz1 = SHF(dz, q1);
                if (cc == 0) {
                    const int r0 = r0s[mt], r1 = r1s[mt];
                    const float wa = w0 + pb2v, wb = w1 + pb2v;
                    atomicAdd(&g_pagg[r0 * 3 + 0], dx0 * wa);
                    atomicAdd(&g_pagg[r0 * 3 + 1], dy0 * wa);
                    atomicAdd(&g_pagg[r0 * 3 + 2], dz0 * wa);
                    atomicAdd(&g_pagg[r1 * 3 + 0], dx1 * wb);
                    atomicAdd(&g_pagg[r1 * 3 + 1], dy1 * wb);
                    atomicAdd(&g_pagg[r1 * 3 + 2], dz1 * wb);
                }
            }
        }
    }
}

// -------- node MMA kernel SMEM layout --------
#define NO_W1  0        // 64n x 68w = 17408 B
#define NO_W2  17408    // 64n x 36w = 9216 B
#define NO_AF  26624    // 256 x 36w = 36864 B
#define NO_AM  63488    // 256 x 36w = 36864 B
#define NO_B1  100352   // 64 f32
#define NO_B2  100608   // 64 f32
#define NSM_TOT 100864

template <bool DO_POS>
__global__ void __launch_bounds__(ETPB)
node_mma_kernel(int featSel, int posSel, int layer,
                const float* __restrict__ nb1, const float* __restrict__ nb2)
{
    extern __shared__ __align__(16) char sm[];
    u32*   N1s = (u32*)(sm + NO_W1);
    u32*   N2s = (u32*)(sm + NO_W2);
    u32*   A_F = (u32*)(sm + NO_AF);
    u32*   A_M = (u32*)(sm + NO_AM);
    float* b1s = (float*)(sm + NO_B1);
    float* b2s = (float*)(sm + NO_B2);

    const int tid = threadIdx.x;

    {
        const u32* wsrc = g_wnb + layer * 6144;
        for (int i = tid; i < 4096; i += ETPB) {
            int n = i >> 6, w = i & 63;
            N1s[n * 68 + w] = wsrc[i];
        }
        for (int i = tid; i < 2048; i += ETPB) {
            int n = i >> 5, w = i & 31;
            N2s[n * 36 + w] = wsrc[4096 + i];
        }
    }
    if (tid < 64) { b1s[tid] = nb1[tid]; b2s[tid] = nb2[tid]; }
    __syncthreads();

    const u32* fin  = featSel ? g_featPB : g_featPA;
    u32*       fout = featSel ? g_featPA : g_featPB;
    const float* posIn  = posSel ? g_posB : g_posA;
    float*       posOut = posSel ? g_posA : g_posB;

    const int lane = tid & 31;
    const int g  = lane >> 2;
    const int cc = lane & 3;
    const int tb = (tid >> 5) * 32;

    const int tile = blockIdx.x;
    const int n = tile * ETPB + tid;
    const bool valid = (n < NN);
    const int nc = valid ? n : (NN - 1);
    const float inv = g_inv[nc];

    // ---- prologue: stage A tiles ----
    {
        const uint4* fr4 = (const uint4*)(fin + (size_t)nc * 32);
        u32* aF = A_F + tid * 36;
#pragma unroll
        for (int q = 0; q < 8; ++q) *(uint4*)(aF + 4 * q) = fr4[q];

        const float4* fm = (const float4*)(g_msg + (size_t)nc * 64);
        u32* aM = A_M + tid * 36;
#pragma unroll
        for (int q = 0; q < 16; ++q) {
            float4 v = fm[q];
            aM[2 * q]     = pk2(v.x * inv, v.y * inv);
            aM[2 * q + 1] = pk2(v.z * inv, v.w * inv);
        }
    }
    if (valid) {
        // zero own msg row for next layer (only the owner writes)
        float4* fm = (float4*)(g_msg + (size_t)n * 64);
        const float4 z4 = make_float4(0.f, 0.f, 0.f, 0.f);
#pragma unroll
        for (int q = 0; q < 16; ++q) fm[q] = z4;
        if (DO_POS) {
            posOut[n * 3 + 0] = posIn[n * 3 + 0] + g_pagg[n * 3 + 0] * inv;
            posOut[n * 3 + 1] = posIn[n * 3 + 1] + g_pagg[n * 3 + 1] * inv;
            posOut[n * 3 + 2] = posIn[n * 3 + 2] + g_pagg[n * 3 + 2] * inv;
            g_pagg[n * 3 + 0] = 0.f;
            g_pagg[n * 3 + 1] = 0.f;
            g_pagg[n * 3 + 2] = 0.f;
        }
    }
    __syncwarp();

    float acc[2][8][4];
#pragma unroll
    for (int mt = 0; mt < 2; ++mt)
#pragma unroll
        for (int nt = 0; nt < 8; ++nt)
#pragma unroll
            for (int i = 0; i < 4; ++i) acc[mt][nt][i] = 0.0f;

    // ---- stage 1: h = silu([feat | msg_mean] @ nW1 + nb1) ----
#pragma unroll
    for (int kt = 0; kt < 4; ++kt) stepK(acc, A_F, N1s, 36, 68, kt * 8, kt * 8, tb, g, cc);
#pragma unroll
    for (int kt = 0; kt < 4; ++kt) stepK(acc, A_M, N1s, 36, 68, kt * 8, 32 + kt * 8, tb, g, cc);

#pragma unroll
    for (int mt = 0; mt < 2; ++mt) {
        const int e0 = tb + mt * 16 + g, e1 = e0 + 8;
#pragma unroll
        for (int nt = 0; nt < 8; ++nt) {
            const int n0 = nt * 8 + 2 * cc;
            float v00 = silu_f(acc[mt][nt][0] + b1s[n0]);
            float v01 = silu_f(acc[mt][nt][1] + b1s[n0 + 1]);
            float v10 = silu_f(acc[mt][nt][2] + b1s[n0]);
            float v11 = silu_f(acc[mt][nt][3] + b1s[n0 + 1]);
            const int word = nt * 4 + cc;
            A_F[e0 * 36 + word] = pk2(v00, v01);
            A_F[e1 * 36 + word] = pk2(v10, v11);
        }
    }
    __syncwarp();

    // ---- stage 2: feat_out = h @ nW2 + nb2 (no activation), write packed ----
#pragma unroll
    for (int mt = 0; mt < 2; ++mt)
#pragma unroll
        for (int nt = 0; nt < 8; ++nt)
#pragma unroll
            for (int i = 0; i < 4; ++i) acc[mt][nt][i] = 0.0f;
#pragma unroll
    for (int kt = 0; kt < 4; ++kt) stepK(acc, A_F, N2s, 36, 36, kt * 8, kt * 8, tb, g, cc);

#pragma unroll
    for (int mt = 0; mt < 2; ++mt) {
        const int m0 = tile * ETPB + tb + mt * 16 + g;
        const int m1 = m0 + 8;
#pragma unroll
        for (int nt = 0; nt < 8; ++nt) {
            const int n0 = nt * 8 + 2 * cc;
            const int word = nt * 4 + cc;
            if (m0 < NN)
                fout[(size_t)m0 * 32 + word] = pk2(acc[mt][nt][0] + b2s[n0], acc[mt][nt][1] + b2s[n0 + 1]);
            if (m1 < NN)
                fout[(size_t)m1 * 32 + word] = pk2(acc[mt][nt][2] + b2s[n0], acc[mt][nt][3] + b2s[n0 + 1]);
        }
    }
}

// ================= helper kernels =================
__global__ void init_kernel(const float* __restrict__ pos) {
    int i = blockIdx.x * blockDim.x + threadIdx.x;
    if (i < NN * 64) g_msg[i] = 0.0f;
    if (i < NN * 3) { g_pagg[i] = 0.0f; g_posB[i] = pos[i]; }
    if (i < NN) g_cnt[i] = 0;
}
__global__ void count_kernel(const int* __restrict__ row) {
    int e = blockIdx.x * blockDim.x + threadIdx.x;
    if (e < EE) atomicAdd(&g_cnt[row[e]], 1);
}
__global__ void prep_kernel(const float* __restrict__ nf, const float* __restrict__ embW,
                            const float* __restrict__ embb,
                            const float* __restrict__ mW1, const float* __restrict__ mW2,
                            const float* __restrict__ pW1,
                            const float* __restrict__ nW1, const float* __restrict__ nW2) {
    int i = blockIdx.x * blockDim.x + threadIdx.x;
    if (i < NN) g_inv[i] = 1.0f / fmaxf((float)g_cnt[i], 1.0f);
    if (i < NN * 32) {
        int n = i >> 5, w = i & 31;
        int J = 2 * w;
        float v0 = nf[2 * n] * embW[J] + nf[2 * n + 1] * embW[64 + J] + embb[J];
        float v1 = nf[2 * n] * embW[J + 1] + nf[2 * n + 1] * embW[64 + J + 1] + embb[J + 1];
        g_featPA[i] = pk2(v0, v1);
    }
    if (i < 5 * 8192) {
        int l = i >> 13, rem = i & 8191;
        u32 out;
        if (rem < 4096) {
            int n = rem >> 6, w = rem & 63;
            int k = 2 * w;
            out = pk2(mW1[l * 131 * 64 + k * 64 + n], mW1[l * 131 * 64 + (k + 1) * 64 + n]);
        } else {
            int rem2 = rem - 4096;
            int mat = rem2 >> 11, idx = rem2 & 2047;
            int n = idx >> 5, w = idx & 31;
            int k = 2 * w;
            const float* src = (mat == 0) ? mW2 : pW1;
            out = pk2(src[l * 4096 + k * 64 + n], src[l * 4096 + (k + 1) * 64 + n]);
        }
        g_wb[i] = out;
    }
    if (i < 5 * 6144) {
        int l = i / 6144, rem = i % 6144;
        u32 out;
        if (rem < 4096) {
            int n = rem >> 6, w = rem & 63;
            int k = 2 * w;
            out = pk2(nW1[l * 8192 + k * 64 + n], nW1[l * 8192 + (k + 1) * 64 + n]);
        } else {
            int idx = rem - 4096;
            int n = idx >> 5, w = idx & 31;
            int k = 2 * w;
            out = pk2(nW2[l * 4096 + k * 64 + n], nW2[l * 4096 + (k + 1) * 64 + n]);
        }
        g_wnb[i] = out;
    }
}
__global__ void pos_final_kernel(float* __restrict__ out) {
    int i = blockIdx.x * blockDim.x + threadIdx.x;
    if (i < NN * 3) {
        int n = i / 3;
        out[i] = g_posA[i] + g_pagg[i] * g_inv[n];
    }
}

extern "C" void kernel_launch(void* const* d_in, const int* in_sizes, int n_in,
                              void* d_out, int out_size)
{
    const float*  node_feat = (const float*)d_in[0];
    const float*  node_pos  = (const float*)d_in[1];
    const float2* edge_attr = (const float2*)d_in[2];
    const int*    row       = (const int*)d_in[3];
    const int*    col       = (const int*)d_in[4];
    const float*  emb_W     = (const float*)d_in[5];
    const float*  emb_b     = (const float*)d_in[6];
    const float*  mW1 = (const float*)d_in[7];
    const float*  mb1 = (const float*)d_in[8];
    const float*  mW2 = (const float*)d_in[9];
    const float*  mb2 = (const float*)d_in[10];
    const float*  pW1 = (const float*)d_in[11];
    const float*  pb1 = (const float*)d_in[12];
    const float*  pW2 = (const float*)d_in[13];
    const float*  pb2 = (const float*)d_in[14];
    const float*  nW1 = (const float*)d_in[15];
    const float*  nb1 = (const float*)d_in[16];
    const float*  nW2 = (const float*)d_in[17];
    const float*  nb2 = (const float*)d_in[18];
    float* out = (float*)d_out;

    cudaFuncSetAttribute(edge_kernel<true, false>, cudaFuncAttributeMaxDynamicSharedMemorySize, SM_TOT);
    cudaFuncSetAttribute(edge_kernel<true, true>,  cudaFuncAttributeMaxDynamicSharedMemorySize, SM_TOT);
    cudaFuncSetAttribute(edge_kernel<false, true>, cudaFuncAttributeMaxDynamicSharedMemorySize, SM_TOT);
    cudaFuncSetAttribute(node_mma_kernel<false>, cudaFuncAttributeMaxDynamicSharedMemorySize, NSM_TOT);
    cudaFuncSetAttribute(node_mma_kernel<true>,  cudaFuncAttributeMaxDynamicSharedMemorySize, NSM_TOT);

    const int ZG = (NN * 64 + 255) / 256;

    init_kernel<<<ZG, 256>>>(node_pos);
    count_kernel<<<(EE + 255) / 256, 256>>>(row);
    prep_kernel<<<ZG, 256>>>(node_feat, emb_W, emb_b, mW1, mW2, pW1, nW1, nW2);

#define EDGE_ARGS(l) edge_attr, row, col, \
        mW1 + (l) * 131 * 64, mb1 + (l) * 64, mb2 + (l) * 64, \
        pb1 + (l) * 64, pW2 + (l) * 64, pb2 + (l)

    // L0 (com_node_feat_net): feat only
    edge_kernel<true, false><<<EGRID, ETPB, SM_TOT>>>(0, 1, 0, EDGE_ARGS(0));
    node_mma_kernel<false><<<NTTILES, ETPB, NSM_TOT>>>(0, 1, 0, nb1 + 0, nb2 + 0);
    // L1
    edge_kernel<true, true><<<EGRID, ETPB, SM_TOT>>>(1, 1, 1, EDGE_ARGS(1));
    node_mma_kernel<true><<<NTTILES, ETPB, NSM_TOT>>>(1, 1, 1, nb1 + 64, nb2 + 64);
    // L2
    edge_kernel<true, true><<<EGRID, ETPB, SM_TOT>>>(0, 0, 2, EDGE_ARGS(2));
    node_mma_kernel<true><<<NTTILES, ETPB, NSM_TOT>>>(0, 0, 2, nb1 + 128, nb2 + 128);
    // L3
    edge_kernel<true, true><<<EGRID, ETPB, SM_TOT>>>(1, 1, 3, EDGE_ARGS(3));
    node_mma_kernel<true><<<NTTILES, ETPB, NSM_TOT>>>(1, 1, 3, nb1 + 192, nb2 + 192);
    // L4: pos only
    edge_kernel<false, true><<<EGRID, ETPB, SM_TOT>>>(0, 0, 4, EDGE_ARGS(4));
    pos_final_kernel<<<(NN * 3 + 255) / 256, 256>>>(out);

#undef EDGE_ARGS
}